// round 1
// baseline (speedup 1.0000x reference)
#include <cuda_runtime.h>

#define EMBED 1024
#define NHEADS 16
#define HDIM 64
#define BATCH 4
#define SEQ 2048
#define MTOT (BATCH * SEQ)   // 8192

// Scratch (static device globals: allowed; no runtime allocation)
__device__ float g_q[(size_t)MTOT * EMBED];
__device__ float g_k[(size_t)MTOT * EMBED];
__device__ float g_v[(size_t)MTOT * EMBED];
__device__ float g_o[(size_t)MTOT * EMBED];

// ---------------------------------------------------------------------------
// C[M,N] = A[M,K] @ W[K,N] + bias[N]
// 64x64 block tile, BK=16, 256 threads, 4x4 register tile per thread.
// ---------------------------------------------------------------------------
__global__ __launch_bounds__(256) void sgemm_bias(
    const float* __restrict__ A, const float* __restrict__ W,
    const float* __restrict__ bias, float* __restrict__ C,
    int M, int N, int K)
{
    __shared__ float As[16][64];   // [k][m] (transposed A tile)
    __shared__ float Ws[16][64];   // [k][n]

    const int t  = threadIdx.x;
    const int tx = t & 15;         // 0..15 -> n
    const int ty = t >> 4;         // 0..15 -> m
    const int row0 = blockIdx.y * 64;
    const int col0 = blockIdx.x * 64;

    // A loading: thread covers (m = t>>2, k = (t&3)*4 .. +3) as one float4
    const int am = t >> 2;
    const int ak = (t & 3) * 4;
    // W loading: thread covers (k = t>>4, n = (t&15)*4 .. +3) as one float4
    const int wk = t >> 4;
    const int wn = (t & 15) * 4;

    const float* Aptr = A + (size_t)(row0 + am) * K + ak;
    const float* Wptr = W + (size_t)wk * N + col0 + wn;

    float acc[4][4] = {};

    for (int k0 = 0; k0 < K; k0 += 16) {
        float4 av = *(const float4*)(Aptr + k0);
        As[ak + 0][am] = av.x;
        As[ak + 1][am] = av.y;
        As[ak + 2][am] = av.z;
        As[ak + 3][am] = av.w;
        *(float4*)&Ws[wk][wn] = *(const float4*)(Wptr + (size_t)k0 * N);
        __syncthreads();

        #pragma unroll
        for (int kk = 0; kk < 16; ++kk) {
            float4 a4 = *(const float4*)&As[kk][ty * 4];
            float4 b4 = *(const float4*)&Ws[kk][tx * 4];
            float a[4] = {a4.x, a4.y, a4.z, a4.w};
            float b[4] = {b4.x, b4.y, b4.z, b4.w};
            #pragma unroll
            for (int i = 0; i < 4; ++i)
                #pragma unroll
                for (int j = 0; j < 4; ++j)
                    acc[i][j] += a[i] * b[j];
        }
        __syncthreads();
    }

    float4 bv = *(const float4*)&bias[col0 + tx * 4];
    #pragma unroll
    for (int i = 0; i < 4; ++i) {
        float4 cv = make_float4(acc[i][0] + bv.x, acc[i][1] + bv.y,
                                acc[i][2] + bv.z, acc[i][3] + bv.w);
        *(float4*)&C[(size_t)(row0 + ty * 4 + i) * N + col0 + tx * 4] = cv;
    }
}

// ---------------------------------------------------------------------------
// Flash attention, fp32. One block = (batch b, head h, 64 query rows).
// Loops over 2048 keys in tiles of 64. Q/K/V/P tiles in dynamic smem.
// Q/K/V are in [B*S, EMBED] layout with head h occupying cols h*64..h*64+63.
// Output written to the same layout (ready for the Wo projection).
// ---------------------------------------------------------------------------
#define FP 68                       // padded row stride (floats) in smem
#define FLASH_SMEM (4 * 64 * FP * 4)  // bytes

__global__ __launch_bounds__(256) void flash_attn(
    const float* __restrict__ q, const float* __restrict__ k,
    const float* __restrict__ v, float* __restrict__ o)
{
    extern __shared__ float sm[];
    float* Qs = sm;                 // [64][FP]  (row, d)  pre-scaled by 1/8
    float* Ks = sm + 64 * FP;       // [64][FP]  (key, d)
    float* Vs = sm + 2 * 64 * FP;   // [64][FP]  (key, d)
    float* Ps = sm + 3 * 64 * FP;   // [64][FP]  (row, key)

    const int t  = threadIdx.x;
    const int tx = t & 15;
    const int ty = t >> 4;
    const int bh = blockIdx.x;      // 0..63
    const int b  = bh >> 4;
    const int h  = bh & 15;
    const int row0 = blockIdx.y * 64;
    const size_t base = ((size_t)b * SEQ) * EMBED + (size_t)h * HDIM;

    // cooperative tile loads: thread covers (r = t>>2, d = (t&3)*16 .. +15)
    const int lr = t >> 2;          // 0..63
    const int ld = (t & 3) * 16;    // 0,16,32,48

    {
        const float* src = q + base + (size_t)(row0 + lr) * EMBED + ld;
        #pragma unroll
        for (int i = 0; i < 4; ++i) {
            float4 vq = *(const float4*)(src + 4 * i);
            vq.x *= 0.125f; vq.y *= 0.125f; vq.z *= 0.125f; vq.w *= 0.125f;
            *(float4*)&Qs[lr * FP + ld + 4 * i] = vq;
        }
    }

    float m[4], l[4], acc[4][4] = {};
    #pragma unroll
    for (int i = 0; i < 4; ++i) { m[i] = -1e30f; l[i] = 0.f; }

    for (int kt = 0; kt < SEQ; kt += 64) {
        __syncthreads();   // previous iter done reading Ks/Vs/Ps (and Qs loaded)
        {
            const float* ksrc = k + base + (size_t)(kt + lr) * EMBED + ld;
            const float* vsrc = v + base + (size_t)(kt + lr) * EMBED + ld;
            #pragma unroll
            for (int i = 0; i < 4; ++i) {
                *(float4*)&Ks[lr * FP + ld + 4 * i] = *(const float4*)(ksrc + 4 * i);
                *(float4*)&Vs[lr * FP + ld + 4 * i] = *(const float4*)(vsrc + 4 * i);
            }
        }
        __syncthreads();

        // S = Q * K^T   (4x4 per thread, inner dim d)
        float s[4][4] = {};
        #pragma unroll
        for (int d = 0; d < HDIM; d += 4) {
            float4 a4[4], b4[4];
            #pragma unroll
            for (int i = 0; i < 4; ++i) a4[i] = *(const float4*)&Qs[(ty * 4 + i) * FP + d];
            #pragma unroll
            for (int j = 0; j < 4; ++j) b4[j] = *(const float4*)&Ks[(tx * 4 + j) * FP + d];
            #pragma unroll
            for (int i = 0; i < 4; ++i)
                #pragma unroll
                for (int j = 0; j < 4; ++j)
                    s[i][j] += a4[i].x * b4[j].x + a4[i].y * b4[j].y
                             + a4[i].z * b4[j].z + a4[i].w * b4[j].w;
        }

        // online softmax (rows distributed over 16 lanes within warp halves)
        #pragma unroll
        for (int i = 0; i < 4; ++i) {
            float rm = fmaxf(fmaxf(s[i][0], s[i][1]), fmaxf(s[i][2], s[i][3]));
            #pragma unroll
            for (int off = 8; off; off >>= 1)
                rm = fmaxf(rm, __shfl_xor_sync(0xffffffffu, rm, off));
            float mn = fmaxf(m[i], rm);
            float alpha = __expf(m[i] - mn);
            m[i] = mn;
            float rs = 0.f;
            #pragma unroll
            for (int j = 0; j < 4; ++j) { s[i][j] = __expf(s[i][j] - mn); rs += s[i][j]; }
            #pragma unroll
            for (int off = 8; off; off >>= 1)
                rs += __shfl_xor_sync(0xffffffffu, rs, off);
            l[i] = l[i] * alpha + rs;
            #pragma unroll
            for (int j = 0; j < 4; ++j) acc[i][j] *= alpha;
            *(float4*)&Ps[(ty * 4 + i) * FP + tx * 4] =
                make_float4(s[i][0], s[i][1], s[i][2], s[i][3]);
        }
        __syncthreads();

        // O += P * V   (inner dim = key index)
        #pragma unroll 8
        for (int j2 = 0; j2 < 64; ++j2) {
            float4 vv = *(const float4*)&Vs[j2 * FP + tx * 4];
            #pragma unroll
            for (int i = 0; i < 4; ++i) {
                float p = Ps[(ty * 4 + i) * FP + j2];
                acc[i][0] += p * vv.x;
                acc[i][1] += p * vv.y;
                acc[i][2] += p * vv.z;
                acc[i][3] += p * vv.w;
            }
        }
    }

    #pragma unroll
    for (int i = 0; i < 4; ++i) {
        float inv = 1.0f / l[i];
        float4 ov = make_float4(acc[i][0] * inv, acc[i][1] * inv,
                                acc[i][2] * inv, acc[i][3] * inv);
        *(float4*)(o + base + (size_t)(row0 + ty * 4 + i) * EMBED + tx * 4) = ov;
    }
}

// ---------------------------------------------------------------------------
extern "C" void kernel_launch(void* const* d_in, const int* in_sizes, int n_in,
                              void* d_out, int out_size)
{
    const float* x  = (const float*)d_in[0];
    const float* Wq = (const float*)d_in[1];
    const float* bq = (const float*)d_in[2];
    const float* Wk = (const float*)d_in[3];
    const float* bk = (const float*)d_in[4];
    const float* Wv = (const float*)d_in[5];
    const float* bv = (const float*)d_in[6];
    const float* Wo = (const float*)d_in[7];
    const float* bo = (const float*)d_in[8];
    float* out = (float*)d_out;

    float *q, *k, *v, *oa;
    cudaGetSymbolAddress((void**)&q,  g_q);
    cudaGetSymbolAddress((void**)&k,  g_k);
    cudaGetSymbolAddress((void**)&v,  g_v);
    cudaGetSymbolAddress((void**)&oa, g_o);

    dim3 ggrid(EMBED / 64, MTOT / 64);   // (16, 128)

    sgemm_bias<<<ggrid, 256>>>(x, Wq, bq, q, MTOT, EMBED, EMBED);
    sgemm_bias<<<ggrid, 256>>>(x, Wk, bk, k, MTOT, EMBED, EMBED);
    sgemm_bias<<<ggrid, 256>>>(x, Wv, bv, v, MTOT, EMBED, EMBED);

    cudaFuncSetAttribute(flash_attn, cudaFuncAttributeMaxDynamicSharedMemorySize,
                         FLASH_SMEM);
    flash_attn<<<dim3(BATCH * NHEADS, SEQ / 64), 256, FLASH_SMEM>>>(q, k, v, oa);

    sgemm_bias<<<ggrid, 256>>>(oa, Wo, bo, out, MTOT, EMBED, EMBED);
}

// round 2
// speedup vs baseline: 2.8610x; 2.8610x over previous
#include <cuda_runtime.h>
#include <cstdint>

#define EMBED 1024
#define NHEADS 16
#define HDIM 64
#define BATCH 4
#define SEQ 2048
#define MTOT (BATCH * SEQ)   // 8192

// Scratch (static device globals: allowed; no runtime allocation)
__device__ float g_q[(size_t)MTOT * EMBED];
__device__ float g_k[(size_t)MTOT * EMBED];
__device__ float g_v[(size_t)MTOT * EMBED];
__device__ float g_o[(size_t)MTOT * EMBED];

// round-to-nearest fp32 -> tf32 (keeps fp32 container, mantissa rounded to 10b)
__device__ __forceinline__ float rna(float x) {
    float r;
    asm("cvt.rna.tf32.f32 %0, %1;" : "=f"(r) : "f"(x));
    return r;
}
__device__ __forceinline__ uint32_t fbits(float x) { return __float_as_uint(x); }

// D += A(16x8) * B(8x8), tf32 inputs, fp32 accum
__device__ __forceinline__ void mma_tf32(float c[4], const uint32_t a[4],
                                         const uint32_t b[2]) {
    asm volatile(
        "mma.sync.aligned.m16n8k8.row.col.f32.tf32.tf32.f32 "
        "{%0,%1,%2,%3}, {%4,%5,%6,%7}, {%8,%9}, {%0,%1,%2,%3};"
        : "+f"(c[0]), "+f"(c[1]), "+f"(c[2]), "+f"(c[3])
        : "r"(a[0]), "r"(a[1]), "r"(a[2]), "r"(a[3]), "r"(b[0]), "r"(b[1]));
}

// ---------------------------------------------------------------------------
// C[M,N] = A[M,K] @ W[K,N] + bias[N]   (tf32 tensor cores)
// 128x128 block, BK=32, 256 threads = 8 warps (4 M x 2 N), warp tile 32x64.
// ---------------------------------------------------------------------------
__global__ __launch_bounds__(256) void sgemm_tc(
    const float* __restrict__ A, const float* __restrict__ W,
    const float* __restrict__ bias, float* __restrict__ C,
    int M, int N, int K)
{
    __shared__ float As[128][36];   // [m][k], pad->conflict-free a-frag loads
    __shared__ float Bs[32][132];   // [k][n]

    const int t = threadIdx.x;
    const int lane = t & 31, warp = t >> 5;
    const int g = lane >> 2, e = lane & 3;
    const int wm = warp & 3, wn = warp >> 2;
    const int m0 = wm * 32, n0 = wn * 64;
    const int row0 = blockIdx.y * 128, col0 = blockIdx.x * 128;

    const int am = t >> 3, ak = (t & 7) * 4;   // A loader: 32 rows/pass
    const int bk = t >> 6, bn = (t & 63) * 2;  // unused alt; real below
    (void)bk; (void)bn;
    const int wk = t >> 5, wn4 = (t & 31) * 4; // B loader: 8 k-rows/pass

    float acc[2][8][4] = {};

    for (int k0 = 0; k0 < K; k0 += 32) {
        __syncthreads();
        #pragma unroll
        for (int p = 0; p < 4; ++p) {
            float4 av = *(const float4*)(A + (size_t)(row0 + am + 32 * p) * K + k0 + ak);
            av.x = rna(av.x); av.y = rna(av.y); av.z = rna(av.z); av.w = rna(av.w);
            *(float4*)&As[am + 32 * p][ak] = av;

            float4 wv = *(const float4*)(W + (size_t)(k0 + wk + 8 * p) * N + col0 + wn4);
            wv.x = rna(wv.x); wv.y = rna(wv.y); wv.z = rna(wv.z); wv.w = rna(wv.w);
            *(float4*)&Bs[wk + 8 * p][wn4] = wv;
        }
        __syncthreads();

        #pragma unroll
        for (int ks = 0; ks < 4; ++ks) {
            const int k8 = ks * 8;
            uint32_t a[2][4];
            #pragma unroll
            for (int mt = 0; mt < 2; ++mt) {
                const int r = m0 + mt * 16 + g;
                a[mt][0] = fbits(As[r][k8 + e]);
                a[mt][1] = fbits(As[r + 8][k8 + e]);
                a[mt][2] = fbits(As[r][k8 + e + 4]);
                a[mt][3] = fbits(As[r + 8][k8 + e + 4]);
            }
            #pragma unroll
            for (int n = 0; n < 8; ++n) {
                uint32_t b[2];
                const int c = n0 + n * 8 + g;
                b[0] = fbits(Bs[k8 + e][c]);
                b[1] = fbits(Bs[k8 + e + 4][c]);
                mma_tf32(acc[0][n], a[0], b);
                mma_tf32(acc[1][n], a[1], b);
            }
        }
    }

    #pragma unroll
    for (int mt = 0; mt < 2; ++mt) {
        const int r = row0 + m0 + mt * 16 + g;
        #pragma unroll
        for (int n = 0; n < 8; ++n) {
            const int c = col0 + n0 + n * 8 + 2 * e;
            const float b0 = bias[c], b1 = bias[c + 1];
            *(float2*)&C[(size_t)r * N + c] =
                make_float2(acc[mt][n][0] + b0, acc[mt][n][1] + b1);
            *(float2*)&C[(size_t)(r + 8) * N + c] =
                make_float2(acc[mt][n][2] + b0, acc[mt][n][3] + b1);
        }
    }
}

// ---------------------------------------------------------------------------
// Flash attention, tf32 tensor cores. Block = (b,h, 128 query rows).
// 8 warps x 16 rows. Bc=64 keys/iter. Online softmax on mma fragments.
// ---------------------------------------------------------------------------
#define FS 68
#define FLASH_SMEM ((128 * FS + 64 * FS + 64 * FS + 128 * FS) * 4)  // 104448 B

__global__ __launch_bounds__(256) void flash_tc(
    const float* __restrict__ q, const float* __restrict__ k,
    const float* __restrict__ v, float* __restrict__ o)
{
    extern __shared__ float sm[];
    float* Qs = sm;                       // [128][FS]  (row, d), *0.125, tf32
    float* Ks = Qs + 128 * FS;            // [64][FS]   (d, key)  TRANSPOSED
    float* Vs = Ks + 64 * FS;             // [64][FS]   (key, d)
    float* Ps = Vs + 64 * FS;             // [128][FS]  (row, key)

    const int t = threadIdx.x;
    const int lane = t & 31, warp = t >> 5;
    const int g = lane >> 2, e = lane & 3;
    const int m0 = warp * 16;

    const int bh = blockIdx.x;
    const int b = bh >> 4, h = bh & 15;
    const int qrow0 = blockIdx.y * 128;
    const size_t base = ((size_t)b * SEQ) * EMBED + (size_t)h * HDIM;

    // load Q block: 128x64 -> 2048 float4s, 8 per thread
    #pragma unroll
    for (int i = 0; i < 8; ++i) {
        const int f = t + 256 * i;
        const int row = f >> 4, d = (f & 15) * 4;
        float4 x = *(const float4*)(q + base + (size_t)(qrow0 + row) * EMBED + d);
        x.x = rna(x.x * 0.125f); x.y = rna(x.y * 0.125f);
        x.z = rna(x.z * 0.125f); x.w = rna(x.w * 0.125f);
        *(float4*)&Qs[row * FS + d] = x;
    }

    float o_[8][4] = {};
    float mrow[2] = {-1e30f, -1e30f}, lrow[2] = {0.f, 0.f};

    for (int kt = 0; kt < SEQ; kt += 64) {
        __syncthreads();   // all warps done with Ks/Vs of previous iter
        #pragma unroll
        for (int i = 0; i < 4; ++i) {
            const int f = t + 256 * i;           // 1024 float4s
            const int key = f >> 4, d = (f & 15) * 4;
            float4 kv = *(const float4*)(k + base + (size_t)(kt + key) * EMBED + d);
            Ks[(d + 0) * FS + key] = rna(kv.x);
            Ks[(d + 1) * FS + key] = rna(kv.y);
            Ks[(d + 2) * FS + key] = rna(kv.z);
            Ks[(d + 3) * FS + key] = rna(kv.w);
            float4 vv = *(const float4*)(v + base + (size_t)(kt + key) * EMBED + d);
            vv.x = rna(vv.x); vv.y = rna(vv.y); vv.z = rna(vv.z); vv.w = rna(vv.w);
            *(float4*)&Vs[key * FS + d] = vv;
        }
        __syncthreads();

        // S = Q * K^T : per-warp 16x64
        float s[8][4] = {};
        #pragma unroll
        for (int ks = 0; ks < 8; ++ks) {
            const int k8 = ks * 8;
            uint32_t a[4];
            a[0] = fbits(Qs[(m0 + g) * FS + k8 + e]);
            a[1] = fbits(Qs[(m0 + g + 8) * FS + k8 + e]);
            a[2] = fbits(Qs[(m0 + g) * FS + k8 + e + 4]);
            a[3] = fbits(Qs[(m0 + g + 8) * FS + k8 + e + 4]);
            #pragma unroll
            for (int n = 0; n < 8; ++n) {
                uint32_t bb[2];
                bb[0] = fbits(Ks[(k8 + e) * FS + n * 8 + g]);
                bb[1] = fbits(Ks[(k8 + e + 4) * FS + n * 8 + g]);
                mma_tf32(s[n], a, bb);
            }
        }

        // online softmax per row-half (c0,c1 -> row g ; c2,c3 -> row g+8)
        #pragma unroll
        for (int hh = 0; hh < 2; ++hh) {
            const int ci = hh * 2;
            float mx = -1e30f;
            #pragma unroll
            for (int n = 0; n < 8; ++n)
                mx = fmaxf(mx, fmaxf(s[n][ci], s[n][ci + 1]));
            mx = fmaxf(mx, __shfl_xor_sync(0xffffffffu, mx, 1));
            mx = fmaxf(mx, __shfl_xor_sync(0xffffffffu, mx, 2));
            const float mn = fmaxf(mrow[hh], mx);
            const float al = __expf(mrow[hh] - mn);
            mrow[hh] = mn;
            float sum = 0.f;
            #pragma unroll
            for (int n = 0; n < 8; ++n) {
                const float p0 = __expf(s[n][ci] - mn);
                const float p1 = __expf(s[n][ci + 1] - mn);
                s[n][ci] = p0; s[n][ci + 1] = p1;
                sum += p0 + p1;
            }
            sum += __shfl_xor_sync(0xffffffffu, sum, 1);
            sum += __shfl_xor_sync(0xffffffffu, sum, 2);
            lrow[hh] = lrow[hh] * al + sum;
            const int pr = (m0 + g + 8 * hh) * FS;
            #pragma unroll
            for (int n = 0; n < 8; ++n) {
                o_[n][ci] *= al; o_[n][ci + 1] *= al;
                Ps[pr + n * 8 + 2 * e]     = rna(s[n][ci]);
                Ps[pr + n * 8 + 2 * e + 1] = rna(s[n][ci + 1]);
            }
        }
        __syncwarp();   // Ps is per-warp private: warp-level fence suffices

        // O += P * V : per-warp 16x64, k-dim = 64 keys
        #pragma unroll
        for (int ks = 0; ks < 8; ++ks) {
            const int k8 = ks * 8;
            uint32_t a[4];
            a[0] = fbits(Ps[(m0 + g) * FS + k8 + e]);
            a[1] = fbits(Ps[(m0 + g + 8) * FS + k8 + e]);
            a[2] = fbits(Ps[(m0 + g) * FS + k8 + e + 4]);
            a[3] = fbits(Ps[(m0 + g + 8) * FS + k8 + e + 4]);
            #pragma unroll
            for (int n = 0; n < 8; ++n) {
                uint32_t bb[2];
                bb[0] = fbits(Vs[(k8 + e) * FS + n * 8 + g]);
                bb[1] = fbits(Vs[(k8 + e + 4) * FS + n * 8 + g]);
                mma_tf32(o_[n], a, bb);
            }
        }
    }

    // epilogue: O /= l, write back into [B*S, EMBED] layout at head offset
    #pragma unroll
    for (int hh = 0; hh < 2; ++hh) {
        const float inv = 1.0f / lrow[hh];
        const int row = qrow0 + m0 + g + 8 * hh;
        const int ci = hh * 2;
        #pragma unroll
        for (int n = 0; n < 8; ++n) {
            *(float2*)(o + base + (size_t)row * EMBED + n * 8 + 2 * e) =
                make_float2(o_[n][ci] * inv, o_[n][ci + 1] * inv);
        }
    }
}

// ---------------------------------------------------------------------------
extern "C" void kernel_launch(void* const* d_in, const int* in_sizes, int n_in,
                              void* d_out, int out_size)
{
    const float* x  = (const float*)d_in[0];
    const float* Wq = (const float*)d_in[1];
    const float* bq = (const float*)d_in[2];
    const float* Wk = (const float*)d_in[3];
    const float* bk = (const float*)d_in[4];
    const float* Wv = (const float*)d_in[5];
    const float* bv = (const float*)d_in[6];
    const float* Wo = (const float*)d_in[7];
    const float* bo = (const float*)d_in[8];
    float* out = (float*)d_out;

    float *q, *k, *v, *oa;
    cudaGetSymbolAddress((void**)&q,  g_q);
    cudaGetSymbolAddress((void**)&k,  g_k);
    cudaGetSymbolAddress((void**)&v,  g_v);
    cudaGetSymbolAddress((void**)&oa, g_o);

    dim3 ggrid(EMBED / 128, MTOT / 128);   // (8, 64)

    sgemm_tc<<<ggrid, 256>>>(x, Wq, bq, q, MTOT, EMBED, EMBED);
    sgemm_tc<<<ggrid, 256>>>(x, Wk, bk, k, MTOT, EMBED, EMBED);
    sgemm_tc<<<ggrid, 256>>>(x, Wv, bv, v, MTOT, EMBED, EMBED);

    cudaFuncSetAttribute(flash_tc, cudaFuncAttributeMaxDynamicSharedMemorySize,
                         FLASH_SMEM);
    flash_tc<<<dim3(BATCH * NHEADS, SEQ / 128), 256, FLASH_SMEM>>>(q, k, v, oa);

    sgemm_tc<<<ggrid, 256>>>(oa, Wo, bo, out, MTOT, EMBED, EMBED);
}

// round 3
// speedup vs baseline: 4.9670x; 1.7361x over previous
#include <cuda_runtime.h>
#include <cstdint>

#define EMBED 1024
#define NHEADS 16
#define HDIM 64
#define BATCH 4
#define SEQ 2048
#define MTOT (BATCH * SEQ)   // 8192

// Scratch (static device globals: allowed; no runtime allocation)
__device__ float g_q [(size_t)MTOT * EMBED];
__device__ float g_k [(size_t)MTOT * EMBED];
__device__ float g_v [(size_t)MTOT * EMBED];
__device__ float g_o [(size_t)MTOT * EMBED];
__device__ float g_xr[(size_t)MTOT * EMBED];
__device__ float g_wq[(size_t)EMBED * EMBED];
__device__ float g_wk[(size_t)EMBED * EMBED];
__device__ float g_wv[(size_t)EMBED * EMBED];
__device__ float g_wo[(size_t)EMBED * EMBED];

__device__ __forceinline__ float rna(float x) {
    float r;
    asm("cvt.rna.tf32.f32 %0, %1;" : "=f"(r) : "f"(x));
    return r;
}
__device__ __forceinline__ uint32_t fbits(float x) { return __float_as_uint(x); }

__device__ __forceinline__ void mma_tf32(float c[4], const uint32_t a[4],
                                         const uint32_t b[2]) {
    asm volatile(
        "mma.sync.aligned.m16n8k8.row.col.f32.tf32.tf32.f32 "
        "{%0,%1,%2,%3}, {%4,%5,%6,%7}, {%8,%9}, {%0,%1,%2,%3};"
        : "+f"(c[0]), "+f"(c[1]), "+f"(c[2]), "+f"(c[3])
        : "r"(a[0]), "r"(a[1]), "r"(a[2]), "r"(a[3]), "r"(b[0]), "r"(b[1]));
}

__device__ __forceinline__ void cp16(float* dst_smem, const float* src) {
    uint32_t d = (uint32_t)__cvta_generic_to_shared(dst_smem);
    asm volatile("cp.async.cg.shared.global [%0], [%1], 16;" :: "r"(d), "l"(src));
}
#define CP_COMMIT() asm volatile("cp.async.commit_group;")
#define CP_WAIT0()  asm volatile("cp.async.wait_group 0;" ::: "memory")

// ---------------------------------------------------------------------------
// elementwise: dst = rna(scale * src), float4-wide
// ---------------------------------------------------------------------------
__global__ void preround(const float* __restrict__ s, float* __restrict__ d,
                         float sc, int n4)
{
    int i = blockIdx.x * 256 + threadIdx.x;
    if (i < n4) {
        float4 v = ((const float4*)s)[i];
        v.x = rna(v.x * sc); v.y = rna(v.y * sc);
        v.z = rna(v.z * sc); v.w = rna(v.w * sc);
        ((float4*)d)[i] = v;
    }
}

// ---------------------------------------------------------------------------
// C[M,N] = A[M,K] @ W[K,N] + bscale*bias[N]    (inputs pre-rounded to tf32)
// 128x128 block, BK=32, 256 threads = 8 warps (4M x 2N), warp tile 32x64.
// cp.async double-buffered smem.  As[2][128][36]  Bs[2][32][136].
// ---------------------------------------------------------------------------
#define GEMM_SMEM ((2 * 128 * 36 + 2 * 32 * 136) * 4)   // 71680 B

__global__ __launch_bounds__(256) void sgemm_cp(
    const float* __restrict__ A, const float* __restrict__ W,
    const float* __restrict__ bias, float* __restrict__ C,
    float bscale, int round_out, int M, int N, int K)
{
    extern __shared__ float sh[];
    float* As = sh;                   // [2][128][36]
    float* Bs = sh + 2 * 128 * 36;    // [2][32][136]

    const int t = threadIdx.x;
    const int lane = t & 31, warp = t >> 5;
    const int g = lane >> 2, e = lane & 3;
    const int wm = warp & 3, wn = warp >> 2;
    const int m0 = wm * 32, n0 = wn * 64;
    const int row0 = blockIdx.y * 128, col0 = blockIdx.x * 128;

    const int am = t >> 3, ak = (t & 7) * 4;     // A: 32 rows/pass, 4 passes
    const int wk = t >> 5, wn4 = (t & 31) * 4;   // B: 8 k-rows/pass, 4 passes

    const float* Abase = A + (size_t)(row0 + am) * K + ak;
    const float* Wbase = W + (size_t)wk * N + col0 + wn4;

    // prefetch tile 0
    #pragma unroll
    for (int p = 0; p < 4; ++p) {
        cp16(&As[(am + 32 * p) * 36 + ak], Abase + (size_t)(32 * p) * K);
        cp16(&Bs[(wk + 8 * p) * 136 + wn4], Wbase + (size_t)(8 * p) * N);
    }
    CP_COMMIT();

    float acc[2][8][4] = {};
    const int NIT = K / 32;

    for (int it = 0; it < NIT; ++it) {
        CP_WAIT0();
        __syncthreads();
        if (it + 1 < NIT) {
            const int nb = (it + 1) & 1;
            const int k0 = (it + 1) * 32;
            #pragma unroll
            for (int p = 0; p < 4; ++p) {
                cp16(&As[nb * 128 * 36 + (am + 32 * p) * 36 + ak],
                     Abase + (size_t)(32 * p) * K + k0);
                cp16(&Bs[nb * 32 * 136 + (wk + 8 * p) * 136 + wn4],
                     Wbase + (size_t)(k0 + 8 * p) * N);
            }
            CP_COMMIT();
        }
        const float* Ab = As + (it & 1) * 128 * 36;
        const float* Bb = Bs + (it & 1) * 32 * 136;

        #pragma unroll
        for (int ks = 0; ks < 4; ++ks) {
            const int k8 = ks * 8;
            uint32_t a[2][4];
            #pragma unroll
            for (int mt = 0; mt < 2; ++mt) {
                const int r = m0 + mt * 16 + g;
                a[mt][0] = fbits(Ab[r * 36 + k8 + e]);
                a[mt][1] = fbits(Ab[(r + 8) * 36 + k8 + e]);
                a[mt][2] = fbits(Ab[r * 36 + k8 + e + 4]);
                a[mt][3] = fbits(Ab[(r + 8) * 36 + k8 + e + 4]);
            }
            #pragma unroll
            for (int n = 0; n < 8; ++n) {
                uint32_t b[2];
                const int c = n0 + n * 8 + g;
                b[0] = fbits(Bb[(k8 + e) * 136 + c]);
                b[1] = fbits(Bb[(k8 + e + 4) * 136 + c]);
                mma_tf32(acc[0][n], a[0], b);
                mma_tf32(acc[1][n], a[1], b);
            }
        }
        __syncthreads();
    }

    #pragma unroll
    for (int mt = 0; mt < 2; ++mt) {
        const int r = row0 + m0 + mt * 16 + g;
        #pragma unroll
        for (int n = 0; n < 8; ++n) {
            const int c = col0 + n0 + n * 8 + 2 * e;
            const float b0 = bias[c] * bscale, b1 = bias[c + 1] * bscale;
            float v00 = acc[mt][n][0] + b0, v01 = acc[mt][n][1] + b1;
            float v10 = acc[mt][n][2] + b0, v11 = acc[mt][n][3] + b1;
            if (round_out) { v00 = rna(v00); v01 = rna(v01);
                             v10 = rna(v10); v11 = rna(v11); }
            *(float2*)&C[(size_t)r * N + c]       = make_float2(v00, v01);
            *(float2*)&C[(size_t)(r + 8) * N + c] = make_float2(v10, v11);
        }
    }
}

// ---------------------------------------------------------------------------
// Flash attention, tf32. Block = (b,h, 256 query rows), 256 threads = 8 warps,
// each warp 32 rows (2 m-tiles). Bc=64. cp.async double-buffered K/V.
// All inputs pre-rounded (Q pre-scaled by 1/8 via Wq).
// smem: Qs[256][68] Ks[2][64][68] Vs[2][64][72] Ps[256][68]  = 210944 B
// ---------------------------------------------------------------------------
#define QS_OFF 0
#define KS_OFF (256 * 68)
#define VS_OFF (KS_OFF + 2 * 64 * 68)
#define PS_OFF (VS_OFF + 2 * 64 * 72)
#define FLASH_SMEM ((PS_OFF + 256 * 68) * 4)

__global__ __launch_bounds__(256) void flash_cp(
    const float* __restrict__ q, const float* __restrict__ k,
    const float* __restrict__ v, float* __restrict__ o)
{
    extern __shared__ float sh[];
    float* Qs = sh + QS_OFF;
    float* Ks = sh + KS_OFF;
    float* Vs = sh + VS_OFF;
    float* Ps = sh + PS_OFF;

    const int t = threadIdx.x;
    const int lane = t & 31, warp = t >> 5;
    const int g = lane >> 2, e = lane & 3;
    const int m0 = warp * 32;

    const int bh = blockIdx.x;
    const int b = bh >> 4, h = bh & 15;
    const int qrow0 = blockIdx.y * 256;
    const size_t base = ((size_t)b * SEQ) * EMBED + (size_t)h * HDIM;

    const int lkey = t >> 4;          // 0..15 (x4 passes -> 64)
    const int lq4  = (t & 15) * 4;    // d offset

    // cp.async K/V tile 0 into buf 0
    #pragma unroll
    for (int i = 0; i < 4; ++i) {
        const int key = lkey + 16 * i;
        cp16(&Ks[key * 68 + lq4], k + base + (size_t)key * EMBED + lq4);
        cp16(&Vs[key * 72 + lq4], v + base + (size_t)key * EMBED + lq4);
    }
    CP_COMMIT();

    // load Q block 256x64 (regular loads, once)
    #pragma unroll
    for (int i = 0; i < 16; ++i) {
        const int row = lkey + 16 * i;
        *(float4*)&Qs[row * 68 + lq4] =
            *(const float4*)(q + base + (size_t)(qrow0 + row) * EMBED + lq4);
    }

    float o_[2][8][4] = {};
    float mrow[2][2], lrow[2][2];
    #pragma unroll
    for (int mt = 0; mt < 2; ++mt)
        #pragma unroll
        for (int hh = 0; hh < 2; ++hh) { mrow[mt][hh] = -1e30f; lrow[mt][hh] = 0.f; }

    const int NIT = SEQ / 64;
    CP_WAIT0();
    __syncthreads();

    for (int it = 0; it < NIT; ++it) {
        const int bf = it & 1;
        if (it + 1 < NIT) {
            const int nb = bf ^ 1;
            const int kt = (it + 1) * 64;
            #pragma unroll
            for (int i = 0; i < 4; ++i) {
                const int key = lkey + 16 * i;
                cp16(&Ks[nb * 64 * 68 + key * 68 + lq4],
                     k + base + (size_t)(kt + key) * EMBED + lq4);
                cp16(&Vs[nb * 64 * 72 + key * 72 + lq4],
                     v + base + (size_t)(kt + key) * EMBED + lq4);
            }
            CP_COMMIT();
        }
        const float* Kb = Ks + bf * 64 * 68;
        const float* Vb = Vs + bf * 64 * 72;

        // S = Q * K^T  : 2 m-tiles x 8 n-tiles, k-dim = 64
        float s[2][8][4] = {};
        #pragma unroll
        for (int ks = 0; ks < 8; ++ks) {
            const int k8 = ks * 8;
            uint32_t a[2][4];
            #pragma unroll
            for (int mt = 0; mt < 2; ++mt) {
                const int r = m0 + mt * 16 + g;
                a[mt][0] = fbits(Qs[r * 68 + k8 + e]);
                a[mt][1] = fbits(Qs[(r + 8) * 68 + k8 + e]);
                a[mt][2] = fbits(Qs[r * 68 + k8 + e + 4]);
                a[mt][3] = fbits(Qs[(r + 8) * 68 + k8 + e + 4]);
            }
            #pragma unroll
            for (int n = 0; n < 8; ++n) {
                uint32_t bb[2];
                bb[0] = fbits(Kb[(n * 8 + g) * 68 + k8 + e]);
                bb[1] = fbits(Kb[(n * 8 + g) * 68 + k8 + e + 4]);
                mma_tf32(s[0][n], a[0], bb);
                mma_tf32(s[1][n], a[1], bb);
            }
        }

        // online softmax per m-tile per row-half; write P (rna) to smem
        #pragma unroll
        for (int mt = 0; mt < 2; ++mt) {
            #pragma unroll
            for (int hh = 0; hh < 2; ++hh) {
                const int ci = hh * 2;
                float mx = -1e30f;
                #pragma unroll
                for (int n = 0; n < 8; ++n)
                    mx = fmaxf(mx, fmaxf(s[mt][n][ci], s[mt][n][ci + 1]));
                mx = fmaxf(mx, __shfl_xor_sync(0xffffffffu, mx, 1));
                mx = fmaxf(mx, __shfl_xor_sync(0xffffffffu, mx, 2));
                const float mn = fmaxf(mrow[mt][hh], mx);
                const float al = __expf(mrow[mt][hh] - mn);
                mrow[mt][hh] = mn;
                float sum = 0.f;
                #pragma unroll
                for (int n = 0; n < 8; ++n) {
                    const float p0 = __expf(s[mt][n][ci] - mn);
                    const float p1 = __expf(s[mt][n][ci + 1] - mn);
                    s[mt][n][ci] = p0; s[mt][n][ci + 1] = p1;
                    sum += p0 + p1;
                }
                sum += __shfl_xor_sync(0xffffffffu, sum, 1);
                sum += __shfl_xor_sync(0xffffffffu, sum, 2);
                lrow[mt][hh] = lrow[mt][hh] * al + sum;
                const int pr = (m0 + mt * 16 + g + 8 * hh) * 68;
                #pragma unroll
                for (int n = 0; n < 8; ++n) {
                    o_[mt][n][ci] *= al; o_[mt][n][ci + 1] *= al;
                    *(float2*)&Ps[pr + n * 8 + 2 * e] =
                        make_float2(rna(s[mt][n][ci]), rna(s[mt][n][ci + 1]));
                }
            }
        }
        __syncwarp();   // Ps rows are per-warp private

        // O += P * V  : k-dim = 64 keys
        #pragma unroll
        for (int ks = 0; ks < 8; ++ks) {
            const int k8 = ks * 8;
            uint32_t a[2][4];
            #pragma unroll
            for (int mt = 0; mt < 2; ++mt) {
                const int r = m0 + mt * 16 + g;
                a[mt][0] = fbits(Ps[r * 68 + k8 + e]);
                a[mt][1] = fbits(Ps[(r + 8) * 68 + k8 + e]);
                a[mt][2] = fbits(Ps[r * 68 + k8 + e + 4]);
                a[mt][3] = fbits(Ps[(r + 8) * 68 + k8 + e + 4]);
            }
            #pragma unroll
            for (int n = 0; n < 8; ++n) {
                uint32_t bb[2];
                bb[0] = fbits(Vb[(k8 + e) * 72 + n * 8 + g]);
                bb[1] = fbits(Vb[(k8 + e + 4) * 72 + n * 8 + g]);
                mma_tf32(o_[0][n], a[0], bb);
                mma_tf32(o_[1][n], a[1], bb);
            }
        }

        CP_WAIT0();
        __syncthreads();   // next tile landed; all readers done with bf
    }

    // epilogue: O /= l, rna, write to [B*S, EMBED] at head offset
    #pragma unroll
    for (int mt = 0; mt < 2; ++mt) {
        #pragma unroll
        for (int hh = 0; hh < 2; ++hh) {
            const float inv = 1.0f / lrow[mt][hh];
            const int row = qrow0 + m0 + mt * 16 + g + 8 * hh;
            const int ci = hh * 2;
            #pragma unroll
            for (int n = 0; n < 8; ++n) {
                *(float2*)(o + base + (size_t)row * EMBED + n * 8 + 2 * e) =
                    make_float2(rna(o_[mt][n][ci] * inv),
                                rna(o_[mt][n][ci + 1] * inv));
            }
        }
    }
}

// ---------------------------------------------------------------------------
extern "C" void kernel_launch(void* const* d_in, const int* in_sizes, int n_in,
                              void* d_out, int out_size)
{
    const float* x  = (const float*)d_in[0];
    const float* Wq = (const float*)d_in[1];
    const float* bq = (const float*)d_in[2];
    const float* Wk = (const float*)d_in[3];
    const float* bk = (const float*)d_in[4];
    const float* Wv = (const float*)d_in[5];
    const float* bv = (const float*)d_in[6];
    const float* Wo = (const float*)d_in[7];
    const float* bo = (const float*)d_in[8];
    float* out = (float*)d_out;

    float *q, *k, *v, *oa, *xr, *wq, *wk, *wv, *wo;
    cudaGetSymbolAddress((void**)&q,  g_q);
    cudaGetSymbolAddress((void**)&k,  g_k);
    cudaGetSymbolAddress((void**)&v,  g_v);
    cudaGetSymbolAddress((void**)&oa, g_o);
    cudaGetSymbolAddress((void**)&xr, g_xr);
    cudaGetSymbolAddress((void**)&wq, g_wq);
    cudaGetSymbolAddress((void**)&wk, g_wk);
    cudaGetSymbolAddress((void**)&wv, g_wv);
    cudaGetSymbolAddress((void**)&wo, g_wo);

    const int nx4 = MTOT * EMBED / 4;
    const int nw4 = EMBED * EMBED / 4;
    preround<<<(nx4 + 255) / 256, 256>>>(x,  xr, 1.0f,   nx4);
    preround<<<(nw4 + 255) / 256, 256>>>(Wq, wq, 0.125f, nw4);
    preround<<<(nw4 + 255) / 256, 256>>>(Wk, wk, 1.0f,   nw4);
    preround<<<(nw4 + 255) / 256, 256>>>(Wv, wv, 1.0f,   nw4);
    preround<<<(nw4 + 255) / 256, 256>>>(Wo, wo, 1.0f,   nw4);

    cudaFuncSetAttribute(sgemm_cp, cudaFuncAttributeMaxDynamicSharedMemorySize,
                         GEMM_SMEM);
    cudaFuncSetAttribute(flash_cp, cudaFuncAttributeMaxDynamicSharedMemorySize,
                         FLASH_SMEM);

    dim3 ggrid(EMBED / 128, MTOT / 128);   // (8, 64)

    sgemm_cp<<<ggrid, 256, GEMM_SMEM>>>(xr, wq, bq, q, 0.125f, 1, MTOT, EMBED, EMBED);
    sgemm_cp<<<ggrid, 256, GEMM_SMEM>>>(xr, wk, bk, k, 1.0f,   1, MTOT, EMBED, EMBED);
    sgemm_cp<<<ggrid, 256, GEMM_SMEM>>>(xr, wv, bv, v, 1.0f,   1, MTOT, EMBED, EMBED);

    flash_cp<<<dim3(BATCH * NHEADS, SEQ / 256), 256, FLASH_SMEM>>>(q, k, v, oa);

    sgemm_cp<<<ggrid, 256, GEMM_SMEM>>>(oa, wo, bo, out, 1.0f, 0, MTOT, EMBED, EMBED);
}

// round 6
// speedup vs baseline: 5.0510x; 1.0169x over previous
#include <cuda_runtime.h>
#include <cstdint>

#define EMBED 1024
#define NHEADS 16
#define HDIM 64
#define BATCH 4
#define SEQ 2048
#define MTOT (BATCH * SEQ)   // 8192

// Scratch (static device globals: allowed; no runtime allocation)
__device__ float g_q [(size_t)MTOT * EMBED];
__device__ float g_k [(size_t)MTOT * EMBED];
__device__ float g_v [(size_t)MTOT * EMBED];
__device__ float g_o [(size_t)MTOT * EMBED];
__device__ float g_xr[(size_t)MTOT * EMBED];
__device__ float g_wt[(size_t)3 * EMBED * EMBED];   // [Wq;Wk;Wv] transposed [N][K]
__device__ float g_wo[(size_t)EMBED * EMBED];       // Wo transposed [N][K]
__device__ float g_bc[3 * EMBED];                   // concat bias (q scaled)

__device__ __forceinline__ float rna(float x) {
    float r;
    asm("cvt.rna.tf32.f32 %0, %1;" : "=f"(r) : "f"(x));
    return r;
}
__device__ __forceinline__ uint32_t fbits(float x) { return __float_as_uint(x); }

__device__ __forceinline__ void mma_tf32(float c[4], const uint32_t a[4],
                                         const uint32_t b[2]) {
    asm volatile(
        "mma.sync.aligned.m16n8k8.row.col.f32.tf32.tf32.f32 "
        "{%0,%1,%2,%3}, {%4,%5,%6,%7}, {%8,%9}, {%0,%1,%2,%3};"
        : "+f"(c[0]), "+f"(c[1]), "+f"(c[2]), "+f"(c[3])
        : "r"(a[0]), "r"(a[1]), "r"(a[2]), "r"(a[3]), "r"(b[0]), "r"(b[1]));
}

__device__ __forceinline__ void cp16(void* dst_smem, const void* src) {
    uint32_t d = (uint32_t)__cvta_generic_to_shared(dst_smem);
    asm volatile("cp.async.cg.shared.global [%0], [%1], 16;" :: "r"(d), "l"(src));
}
#define CP_COMMIT() asm volatile("cp.async.commit_group;")
#define CP_WAIT0()  asm volatile("cp.async.wait_group 0;" ::: "memory")

// ---------------------------------------------------------------------------
// elementwise rna (for x)
// ---------------------------------------------------------------------------
__global__ void preround(const float* __restrict__ s, float* __restrict__ d,
                         float sc, int n4)
{
    int i = blockIdx.x * 256 + threadIdx.x;
    if (i < n4) {
        float4 v = ((const float4*)s)[i];
        v.x = rna(v.x * sc); v.y = rna(v.y * sc);
        v.z = rna(v.z * sc); v.w = rna(v.w * sc);
        ((float4*)d)[i] = v;
    }
}

// ---------------------------------------------------------------------------
// transpose + rna:  dst[n][k] = rna(src[k][n] * sc)      (EMBED x EMBED)
// ---------------------------------------------------------------------------
__global__ __launch_bounds__(256) void transpose_rna(
    const float* __restrict__ src, float* __restrict__ dst, float sc)
{
    __shared__ float tl[32][33];
    const int tx = threadIdx.x & 31, ty = threadIdx.x >> 5;  // 32 x 8
    const int x0 = blockIdx.x * 32, y0 = blockIdx.y * 32;
    #pragma unroll
    for (int j = 0; j < 32; j += 8)
        tl[ty + j][tx] = rna(src[(size_t)(y0 + ty + j) * EMBED + x0 + tx] * sc);
    __syncthreads();
    #pragma unroll
    for (int j = 0; j < 32; j += 8)
        dst[(size_t)(x0 + ty + j) * EMBED + y0 + tx] = tl[tx][ty + j];
}

// bias concat: bc[0:1024)=bq*0.125, [1024:2048)=bk, [2048:3072)=bv
__global__ void bias_cat(const float* __restrict__ bq, const float* __restrict__ bk,
                         const float* __restrict__ bv, float* __restrict__ bc)
{
    int i = blockIdx.x * 256 + threadIdx.x;
    if (i < EMBED)          bc[i] = bq[i] * 0.125f;
    else if (i < 2 * EMBED) bc[i] = bk[i - EMBED];
    else if (i < 3 * EMBED) bc[i] = bv[i - 2 * EMBED];
}

// ---------------------------------------------------------------------------
// tf32 mma.sync GEMM: D[M, 128-col block] = A[M,1024] @ BT[n][k]^T + bias
// Block tile 256x128, 256 threads = 8 warps (4M x 2N), warp tile 64x64
// (mt=4, nt=8). BK=32, 2-stage cp.async.  Output routed to D0/D1/D2 by
// n-block index (8 col-blocks of 128 per matrix).
// smem: As[2][256][36] + Bs[2][128][36]  (both staged [row][k], pad 36)
// ---------------------------------------------------------------------------
#define GEMM_SMEM ((2 * 256 * 36 + 2 * 128 * 36) * 4)   // 110592 B

__global__ __launch_bounds__(256) void gemm_big(
    const float* __restrict__ A, const float* __restrict__ BT,
    const float* __restrict__ bias, float* __restrict__ D0,
    float* __restrict__ D1, float* __restrict__ D2, int round_out)
{
    extern __shared__ float sh[];
    float* As = sh;                    // [2][256][36]
    float* Bs = sh + 2 * 256 * 36;     // [2][128][36]

    const int t = threadIdx.x;
    const int lane = t & 31, warp = t >> 5;
    const int g = lane >> 2, e = lane & 3;
    const int wm = warp & 3, wn = warp >> 2;
    const int m0 = wm * 64, n0 = wn * 64;

    const int row0 = blockIdx.y * 256;
    const int bx = blockIdx.x;
    const int id = bx >> 3;                       // which output matrix
    const int col0 = (bx & 7) * 128;              // col within matrix
    float* D = (id == 0) ? D0 : (id == 1) ? D1 : D2;

    // loaders: both tiles staged [row][k], thread covers (row=t>>3 (+32p), k=(t&7)*4)
    const int lr = t >> 3, lk = (t & 7) * 4;
    const float* Ab = A  + (size_t)(row0 + lr) * EMBED + lk;
    const float* Bb = BT + (size_t)(bx * 128 + lr) * EMBED + lk;

    #define GREFILL(k0, buf) do {                                              \
        float* sA = As + (buf) * 256 * 36;                                     \
        float* sB = Bs + (buf) * 128 * 36;                                     \
        _Pragma("unroll")                                                      \
        for (int p = 0; p < 8; ++p)                                            \
            cp16(&sA[(lr + 32 * p) * 36 + lk], Ab + (size_t)(32 * p) * EMBED + (k0)); \
        _Pragma("unroll")                                                      \
        for (int p = 0; p < 4; ++p)                                            \
            cp16(&sB[(lr + 32 * p) * 36 + lk], Bb + (size_t)(32 * p) * EMBED + (k0)); \
        CP_COMMIT();                                                           \
    } while (0)

    GREFILL(0, 0);

    float acc[4][8][4] = {};
    const int NIT = EMBED / 32;

    for (int it = 0; it < NIT; ++it) {
        CP_WAIT0();
        __syncthreads();
        if (it + 1 < NIT) GREFILL((it + 1) * 32, (it + 1) & 1);

        const float* Ac = As + (it & 1) * 256 * 36;
        const float* Bc = Bs + (it & 1) * 128 * 36;

        #pragma unroll
        for (int ks = 0; ks < 4; ++ks) {
            const int k8 = ks * 8;
            uint32_t a[4][4];
            #pragma unroll
            for (int mt = 0; mt < 4; ++mt) {
                const int r = m0 + mt * 16 + g;
                a[mt][0] = fbits(Ac[r * 36 + k8 + e]);
                a[mt][1] = fbits(Ac[(r + 8) * 36 + k8 + e]);
                a[mt][2] = fbits(Ac[r * 36 + k8 + e + 4]);
                a[mt][3] = fbits(Ac[(r + 8) * 36 + k8 + e + 4]);
            }
            #pragma unroll
            for (int n = 0; n < 8; ++n) {
                uint32_t b[2];
                const int br = n0 + n * 8 + g;
                b[0] = fbits(Bc[br * 36 + k8 + e]);
                b[1] = fbits(Bc[br * 36 + k8 + e + 4]);
                #pragma unroll
                for (int mt = 0; mt < 4; ++mt)
                    mma_tf32(acc[mt][n], a[mt], b);
            }
        }
        __syncthreads();
    }

    // epilogue
    #pragma unroll
    for (int mt = 0; mt < 4; ++mt) {
        const int r = row0 + m0 + mt * 16 + g;
        #pragma unroll
        for (int n = 0; n < 8; ++n) {
            const int cl = col0 + n0 + n * 8 + 2 * e;         // col in matrix
            const int cb = bx * 128 + n0 + n * 8 + 2 * e;     // col in bias buf
            const float b0 = bias[cb], b1 = bias[cb + 1];
            float v00 = acc[mt][n][0] + b0, v01 = acc[mt][n][1] + b1;
            float v10 = acc[mt][n][2] + b0, v11 = acc[mt][n][3] + b1;
            if (round_out) { v00 = rna(v00); v01 = rna(v01);
                             v10 = rna(v10); v11 = rna(v11); }
            *(float2*)&D[(size_t)r * EMBED + cl]       = make_float2(v00, v01);
            *(float2*)&D[(size_t)(r + 8) * EMBED + cl] = make_float2(v10, v11);
        }
    }
}

// ---------------------------------------------------------------------------
// Flash attention (unchanged from Round 3 — tf32 mma.sync, cp.async 2-stage)
// ---------------------------------------------------------------------------
#define QS_OFF 0
#define KS_OFF (256 * 68)
#define VS_OFF (KS_OFF + 2 * 64 * 68)
#define PS_OFF (VS_OFF + 2 * 64 * 72)
#define FLASH_SMEM ((PS_OFF + 256 * 68) * 4)

__global__ __launch_bounds__(256) void flash_cp(
    const float* __restrict__ q, const float* __restrict__ k,
    const float* __restrict__ v, float* __restrict__ o)
{
    extern __shared__ float shf[];
    float* Qs = shf + QS_OFF;
    float* Ks = shf + KS_OFF;
    float* Vs = shf + VS_OFF;
    float* Ps = shf + PS_OFF;

    const int t = threadIdx.x;
    const int lane = t & 31, warp = t >> 5;
    const int g = lane >> 2, e = lane & 3;
    const int m0 = warp * 32;

    const int bh = blockIdx.x;
    const int b = bh >> 4, h = bh & 15;
    const int qrow0 = blockIdx.y * 256;
    const size_t base = ((size_t)b * SEQ) * EMBED + (size_t)h * HDIM;

    const int lkey = t >> 4;
    const int lq4  = (t & 15) * 4;

    #pragma unroll
    for (int i = 0; i < 4; ++i) {
        const int key = lkey + 16 * i;
        cp16(&Ks[key * 68 + lq4], k + base + (size_t)key * EMBED + lq4);
        cp16(&Vs[key * 72 + lq4], v + base + (size_t)key * EMBED + lq4);
    }
    CP_COMMIT();

    #pragma unroll
    for (int i = 0; i < 16; ++i) {
        const int row = lkey + 16 * i;
        *(float4*)&Qs[row * 68 + lq4] =
            *(const float4*)(q + base + (size_t)(qrow0 + row) * EMBED + lq4);
    }

    float o_[2][8][4] = {};
    float mrow[2][2], lrow[2][2];
    #pragma unroll
    for (int mt = 0; mt < 2; ++mt)
        #pragma unroll
        for (int hh = 0; hh < 2; ++hh) { mrow[mt][hh] = -1e30f; lrow[mt][hh] = 0.f; }

    const int NIT = SEQ / 64;
    CP_WAIT0();
    __syncthreads();

    for (int it = 0; it < NIT; ++it) {
        const int bf = it & 1;
        if (it + 1 < NIT) {
            const int nb = bf ^ 1;
            const int kt = (it + 1) * 64;
            #pragma unroll
            for (int i = 0; i < 4; ++i) {
                const int key = lkey + 16 * i;
                cp16(&Ks[nb * 64 * 68 + key * 68 + lq4],
                     k + base + (size_t)(kt + key) * EMBED + lq4);
                cp16(&Vs[nb * 64 * 72 + key * 72 + lq4],
                     v + base + (size_t)(kt + key) * EMBED + lq4);
            }
            CP_COMMIT();
        }
        const float* Kb = Ks + bf * 64 * 68;
        const float* Vb = Vs + bf * 64 * 72;

        float s[2][8][4] = {};
        #pragma unroll
        for (int ks = 0; ks < 8; ++ks) {
            const int k8 = ks * 8;
            uint32_t a[2][4];
            #pragma unroll
            for (int mt = 0; mt < 2; ++mt) {
                const int r = m0 + mt * 16 + g;
                a[mt][0] = fbits(Qs[r * 68 + k8 + e]);
                a[mt][1] = fbits(Qs[(r + 8) * 68 + k8 + e]);
                a[mt][2] = fbits(Qs[r * 68 + k8 + e + 4]);
                a[mt][3] = fbits(Qs[(r + 8) * 68 + k8 + e + 4]);
            }
            #pragma unroll
            for (int n = 0; n < 8; ++n) {
                uint32_t bb[2];
                bb[0] = fbits(Kb[(n * 8 + g) * 68 + k8 + e]);
                bb[1] = fbits(Kb[(n * 8 + g) * 68 + k8 + e + 4]);
                mma_tf32(s[0][n], a[0], bb);
                mma_tf32(s[1][n], a[1], bb);
            }
        }

        #pragma unroll
        for (int mt = 0; mt < 2; ++mt) {
            #pragma unroll
            for (int hh = 0; hh < 2; ++hh) {
                const int ci = hh * 2;
                float mx = -1e30f;
                #pragma unroll
                for (int n = 0; n < 8; ++n)
                    mx = fmaxf(mx, fmaxf(s[mt][n][ci], s[mt][n][ci + 1]));
                mx = fmaxf(mx, __shfl_xor_sync(0xffffffffu, mx, 1));
                mx = fmaxf(mx, __shfl_xor_sync(0xffffffffu, mx, 2));
                const float mn = fmaxf(mrow[mt][hh], mx);
                const float al = __expf(mrow[mt][hh] - mn);
                mrow[mt][hh] = mn;
                float sum = 0.f;
                #pragma unroll
                for (int n = 0; n < 8; ++n) {
                    const float p0 = __expf(s[mt][n][ci] - mn);
                    const float p1 = __expf(s[mt][n][ci + 1] - mn);
                    s[mt][n][ci] = p0; s[mt][n][ci + 1] = p1;
                    sum += p0 + p1;
                }
                sum += __shfl_xor_sync(0xffffffffu, sum, 1);
                sum += __shfl_xor_sync(0xffffffffu, sum, 2);
                lrow[mt][hh] = lrow[mt][hh] * al + sum;
                const int pr = (m0 + mt * 16 + g + 8 * hh) * 68;
                #pragma unroll
                for (int n = 0; n < 8; ++n) {
                    o_[mt][n][ci] *= al; o_[mt][n][ci + 1] *= al;
                    *(float2*)&Ps[pr + n * 8 + 2 * e] =
                        make_float2(rna(s[mt][n][ci]), rna(s[mt][n][ci + 1]));
                }
            }
        }
        __syncwarp();

        #pragma unroll
        for (int ks = 0; ks < 8; ++ks) {
            const int k8 = ks * 8;
            uint32_t a[2][4];
            #pragma unroll
            for (int mt = 0; mt < 2; ++mt) {
                const int r = m0 + mt * 16 + g;
                a[mt][0] = fbits(Ps[r * 68 + k8 + e]);
                a[mt][1] = fbits(Ps[(r + 8) * 68 + k8 + e]);
                a[mt][2] = fbits(Ps[r * 68 + k8 + e + 4]);
                a[mt][3] = fbits(Ps[(r + 8) * 68 + k8 + e + 4]);
            }
            #pragma unroll
            for (int n = 0; n < 8; ++n) {
                uint32_t bb[2];
                bb[0] = fbits(Vb[(k8 + e) * 72 + n * 8 + g]);
                bb[1] = fbits(Vb[(k8 + e + 4) * 72 + n * 8 + g]);
                mma_tf32(o_[0][n], a[0], bb);
                mma_tf32(o_[1][n], a[1], bb);
            }
        }

        CP_WAIT0();
        __syncthreads();
    }

    #pragma unroll
    for (int mt = 0; mt < 2; ++mt) {
        #pragma unroll
        for (int hh = 0; hh < 2; ++hh) {
            const float inv = 1.0f / lrow[mt][hh];
            const int row = qrow0 + m0 + mt * 16 + g + 8 * hh;
            const int ci = hh * 2;
            #pragma unroll
            for (int n = 0; n < 8; ++n) {
                *(float2*)(o + base + (size_t)row * EMBED + n * 8 + 2 * e) =
                    make_float2(rna(o_[mt][n][ci] * inv),
                                rna(o_[mt][n][ci + 1] * inv));
            }
        }
    }
}

// ---------------------------------------------------------------------------
extern "C" void kernel_launch(void* const* d_in, const int* in_sizes, int n_in,
                              void* d_out, int out_size)
{
    const float* x  = (const float*)d_in[0];
    const float* Wq = (const float*)d_in[1];
    const float* bq = (const float*)d_in[2];
    const float* Wk = (const float*)d_in[3];
    const float* bk = (const float*)d_in[4];
    const float* Wv = (const float*)d_in[5];
    const float* bv = (const float*)d_in[6];
    const float* Wo = (const float*)d_in[7];
    const float* bo = (const float*)d_in[8];
    float* out = (float*)d_out;

    float *q, *k, *v, *oa, *xr, *wt, *wo, *bc;
    cudaGetSymbolAddress((void**)&q,  g_q);
    cudaGetSymbolAddress((void**)&k,  g_k);
    cudaGetSymbolAddress((void**)&v,  g_v);
    cudaGetSymbolAddress((void**)&oa, g_o);
    cudaGetSymbolAddress((void**)&xr, g_xr);
    cudaGetSymbolAddress((void**)&wt, g_wt);
    cudaGetSymbolAddress((void**)&wo, g_wo);
    cudaGetSymbolAddress((void**)&bc, g_bc);

    const int nx4 = MTOT * EMBED / 4;
    preround<<<(nx4 + 255) / 256, 256>>>(x, xr, 1.0f, nx4);
    dim3 tgrid(EMBED / 32, EMBED / 32);
    transpose_rna<<<tgrid, 256>>>(Wq, wt, 0.125f);
    transpose_rna<<<tgrid, 256>>>(Wk, wt + (size_t)EMBED * EMBED, 1.0f);
    transpose_rna<<<tgrid, 256>>>(Wv, wt + (size_t)2 * EMBED * EMBED, 1.0f);
    transpose_rna<<<tgrid, 256>>>(Wo, wo, 1.0f);
    bias_cat<<<(3 * EMBED + 255) / 256, 256>>>(bq, bk, bv, bc);

    cudaFuncSetAttribute(gemm_big, cudaFuncAttributeMaxDynamicSharedMemorySize,
                         GEMM_SMEM);
    cudaFuncSetAttribute(flash_cp, cudaFuncAttributeMaxDynamicSharedMemorySize,
                         FLASH_SMEM);

    // fused QKV: grid (24, 32); Wo: grid (8, 32)
    gemm_big<<<dim3(24, MTOT / 256), 256, GEMM_SMEM>>>(xr, wt, bc, q, k, v, 1);

    flash_cp<<<dim3(BATCH * NHEADS, SEQ / 256), 256, FLASH_SMEM>>>(q, k, v, oa);

    gemm_big<<<dim3(8, MTOT / 256), 256, GEMM_SMEM>>>(oa, wo, bo, out, out, out, 0);
}

// round 7
// speedup vs baseline: 5.4787x; 1.0847x over previous
#include <cuda_runtime.h>
#include <cstdint>

#define EMBED 1024
#define NHEADS 16
#define HDIM 64
#define BATCH 4
#define SEQ 2048
#define MTOT (BATCH * SEQ)   // 8192

// Scratch (static device globals: allowed; no runtime allocation)
__device__ float g_q [(size_t)MTOT * EMBED];
__device__ float g_k [(size_t)MTOT * EMBED];
__device__ float g_v [(size_t)MTOT * EMBED];
__device__ float g_o [(size_t)MTOT * EMBED];
__device__ float g_xr[(size_t)MTOT * EMBED];
__device__ float g_wt[(size_t)3 * EMBED * EMBED];   // [Wq;Wk;Wv] transposed [N][K]
__device__ float g_wo[(size_t)EMBED * EMBED];       // Wo transposed [N][K]
__device__ float g_bc[3 * EMBED];                   // concat bias (q scaled)

__device__ __forceinline__ float rna(float x) {
    float r;
    asm("cvt.rna.tf32.f32 %0, %1;" : "=f"(r) : "f"(x));
    return r;
}
__device__ __forceinline__ uint32_t fbits(float x) { return __float_as_uint(x); }

__device__ __forceinline__ void mma_tf32(float c[4], const uint32_t a[4],
                                         const uint32_t b[2]) {
    asm volatile(
        "mma.sync.aligned.m16n8k8.row.col.f32.tf32.tf32.f32 "
        "{%0,%1,%2,%3}, {%4,%5,%6,%7}, {%8,%9}, {%0,%1,%2,%3};"
        : "+f"(c[0]), "+f"(c[1]), "+f"(c[2]), "+f"(c[3])
        : "r"(a[0]), "r"(a[1]), "r"(a[2]), "r"(a[3]), "r"(b[0]), "r"(b[1]));
}

__device__ __forceinline__ void cp16(void* dst_smem, const void* src) {
    uint32_t d = (uint32_t)__cvta_generic_to_shared(dst_smem);
    asm volatile("cp.async.cg.shared.global [%0], [%1], 16;" :: "r"(d), "l"(src));
}
#define CP_COMMIT() asm volatile("cp.async.commit_group;")
#define CP_WAIT0()  asm volatile("cp.async.wait_group 0;" ::: "memory")

// ---------------------------------------------------------------------------
// elementwise rna (for x)
// ---------------------------------------------------------------------------
__global__ void preround(const float* __restrict__ s, float* __restrict__ d,
                         float sc, int n4)
{
    int i = blockIdx.x * 256 + threadIdx.x;
    if (i < n4) {
        float4 v = ((const float4*)s)[i];
        v.x = rna(v.x * sc); v.y = rna(v.y * sc);
        v.z = rna(v.z * sc); v.w = rna(v.w * sc);
        ((float4*)d)[i] = v;
    }
}

// ---------------------------------------------------------------------------
// all 4 weight transposes in one launch (z picks matrix); Wq folded * 1/8
// ---------------------------------------------------------------------------
__global__ __launch_bounds__(256) void transpose_all(
    const float* __restrict__ Wq, const float* __restrict__ Wk,
    const float* __restrict__ Wv, const float* __restrict__ Wo,
    float* __restrict__ wt, float* __restrict__ wo)
{
    __shared__ float tl[32][33];
    const int z = blockIdx.z;
    const float* src = (z == 0) ? Wq : (z == 1) ? Wk : (z == 2) ? Wv : Wo;
    float* dst = (z == 3) ? wo : wt + (size_t)z * EMBED * EMBED;
    const float sc = (z == 0) ? 0.125f : 1.0f;

    const int tx = threadIdx.x & 31, ty = threadIdx.x >> 5;  // 32 x 8
    const int x0 = blockIdx.x * 32, y0 = blockIdx.y * 32;
    #pragma unroll
    for (int j = 0; j < 32; j += 8)
        tl[ty + j][tx] = rna(src[(size_t)(y0 + ty + j) * EMBED + x0 + tx] * sc);
    __syncthreads();
    #pragma unroll
    for (int j = 0; j < 32; j += 8)
        dst[(size_t)(x0 + ty + j) * EMBED + y0 + tx] = tl[tx][ty + j];
}

// bias concat: bc[0:1024)=bq*0.125, [1024:2048)=bk, [2048:3072)=bv
__global__ void bias_cat(const float* __restrict__ bq, const float* __restrict__ bk,
                         const float* __restrict__ bv, float* __restrict__ bc)
{
    int i = blockIdx.x * 256 + threadIdx.x;
    if (i < EMBED)          bc[i] = bq[i] * 0.125f;
    else if (i < 2 * EMBED) bc[i] = bk[i - EMBED];
    else if (i < 3 * EMBED) bc[i] = bv[i - 2 * EMBED];
}

// ---------------------------------------------------------------------------
// tf32 mma.sync GEMM: block tile 128x128, 256 thr = 8 warps (4M x 2N),
// warp tile 32x64 (mt=2, nt=8), BK=32, 2-stage cp.async, 2 CTAs/SM.
// Fused-QKV output routing by n-block index (8 col-blocks of 128 / matrix).
// smem: As[2][128][36] + Bs[2][128][36] (both [row][k], pad 36) = 73728 B
// ---------------------------------------------------------------------------
#define GEMM_SMEM (2 * 2 * 128 * 36 * 4)

__global__ __launch_bounds__(256, 2) void gemm_big(
    const float* __restrict__ A, const float* __restrict__ BT,
    const float* __restrict__ bias, float* __restrict__ D0,
    float* __restrict__ D1, float* __restrict__ D2, int round_out)
{
    extern __shared__ float sh[];
    float* As = sh;                    // [2][128][36]
    float* Bs = sh + 2 * 128 * 36;     // [2][128][36]

    const int t = threadIdx.x;
    const int lane = t & 31, warp = t >> 5;
    const int g = lane >> 2, e = lane & 3;
    const int m0 = (warp & 3) * 32, n0 = (warp >> 2) * 64;

    const int row0 = blockIdx.y * 128;
    const int bx = blockIdx.x;
    const int id = bx >> 3;                       // which output matrix
    const int col0 = (bx & 7) * 128;              // col within matrix
    float* D = (id == 0) ? D0 : (id == 1) ? D1 : D2;

    // loaders: tiles staged [row][k]; thread covers (row = t>>3 (+32p), k=(t&7)*4)
    const int lr = t >> 3, lk = (t & 7) * 4;
    const float* Ab = A  + (size_t)(row0 + lr) * EMBED + lk;
    const float* Bb = BT + (size_t)(bx * 128 + lr) * EMBED + lk;

    #define GREFILL(k0, buf) do {                                              \
        float* sA = As + (buf) * 128 * 36;                                     \
        float* sB = Bs + (buf) * 128 * 36;                                     \
        _Pragma("unroll")                                                      \
        for (int p = 0; p < 4; ++p) {                                          \
            cp16(&sA[(lr + 32 * p) * 36 + lk], Ab + (size_t)(32 * p) * EMBED + (k0)); \
            cp16(&sB[(lr + 32 * p) * 36 + lk], Bb + (size_t)(32 * p) * EMBED + (k0)); \
        }                                                                      \
        CP_COMMIT();                                                           \
    } while (0)

    GREFILL(0, 0);

    float acc[2][8][4] = {};
    const int NIT = EMBED / 32;

    for (int it = 0; it < NIT; ++it) {
        CP_WAIT0();
        __syncthreads();
        if (it + 1 < NIT) GREFILL((it + 1) * 32, (it + 1) & 1);

        const float* Ac = As + (it & 1) * 128 * 36;
        const float* Bc = Bs + (it & 1) * 128 * 36;

        #pragma unroll
        for (int ks = 0; ks < 4; ++ks) {
            const int k8 = ks * 8;
            uint32_t a[2][4];
            #pragma unroll
            for (int mt = 0; mt < 2; ++mt) {
                const int r = m0 + mt * 16 + g;
                a[mt][0] = fbits(Ac[r * 36 + k8 + e]);
                a[mt][1] = fbits(Ac[(r + 8) * 36 + k8 + e]);
                a[mt][2] = fbits(Ac[r * 36 + k8 + e + 4]);
                a[mt][3] = fbits(Ac[(r + 8) * 36 + k8 + e + 4]);
            }
            #pragma unroll
            for (int n = 0; n < 8; ++n) {
                uint32_t b[2];
                const int br = n0 + n * 8 + g;
                b[0] = fbits(Bc[br * 36 + k8 + e]);
                b[1] = fbits(Bc[br * 36 + k8 + e + 4]);
                mma_tf32(acc[0][n], a[0], b);
                mma_tf32(acc[1][n], a[1], b);
            }
        }
        __syncthreads();
    }

    // epilogue
    #pragma unroll
    for (int mt = 0; mt < 2; ++mt) {
        const int r = row0 + m0 + mt * 16 + g;
        #pragma unroll
        for (int n = 0; n < 8; ++n) {
            const int cl = col0 + n0 + n * 8 + 2 * e;         // col in matrix
            const int cb = bx * 128 + n0 + n * 8 + 2 * e;     // col in bias buf
            const float b0 = bias[cb], b1 = bias[cb + 1];
            float v00 = acc[mt][n][0] + b0, v01 = acc[mt][n][1] + b1;
            float v10 = acc[mt][n][2] + b0, v11 = acc[mt][n][3] + b1;
            if (round_out) { v00 = rna(v00); v01 = rna(v01);
                             v10 = rna(v10); v11 = rna(v11); }
            *(float2*)&D[(size_t)r * EMBED + cl]       = make_float2(v00, v01);
            *(float2*)&D[(size_t)(r + 8) * EMBED + cl] = make_float2(v10, v11);
        }
    }
}

// ---------------------------------------------------------------------------
// Flash attention v3: Q-block 128 rows, 8 warps x 16 rows (1 m-tile/warp).
// Q fragments hoisted to registers (loaded once via Ps staging).
// Bc=64, 2-stage cp.async K/V. 2 CTAs/SM.
// smem: Ks[2][64][68] Vs[2][64][72] Ps[128][68] = 106496 B
// ---------------------------------------------------------------------------
#define FKS_OFF 0
#define FVS_OFF (2 * 64 * 68)
#define FPS_OFF (FVS_OFF + 2 * 64 * 72)
#define FLASH_SMEM ((FPS_OFF + 128 * 68) * 4)

__global__ __launch_bounds__(256, 2) void flash_v3(
    const float* __restrict__ q, const float* __restrict__ k,
    const float* __restrict__ v, float* __restrict__ o)
{
    extern __shared__ float shf[];
    float* Ks = shf + FKS_OFF;
    float* Vs = shf + FVS_OFF;
    float* Ps = shf + FPS_OFF;

    const int t = threadIdx.x;
    const int lane = t & 31, warp = t >> 5;
    const int g = lane >> 2, e = lane & 3;
    const int m0 = warp * 16;

    const int bh = blockIdx.x;
    const int b = bh >> 4, h = bh & 15;
    const int qrow0 = blockIdx.y * 128;
    const size_t base = ((size_t)b * SEQ) * EMBED + (size_t)h * HDIM;

    const int lkey = t >> 4;          // 0..15
    const int lq4  = (t & 15) * 4;    // 0..60

    // prefetch K/V tile 0 into buf 0
    #pragma unroll
    for (int i = 0; i < 4; ++i) {
        const int key = lkey + 16 * i;
        cp16(&Ks[key * 68 + lq4], k + base + (size_t)key * EMBED + lq4);
        cp16(&Vs[key * 72 + lq4], v + base + (size_t)key * EMBED + lq4);
    }
    CP_COMMIT();

    // stage Q (128x64) into Ps, coalesced, then hoist fragments to registers
    #pragma unroll
    for (int i = 0; i < 8; ++i) {
        const int row = lkey + 16 * i;
        *(float4*)&Ps[row * 68 + lq4] =
            *(const float4*)(q + base + (size_t)(qrow0 + row) * EMBED + lq4);
    }
    __syncthreads();
    uint32_t qa[8][4];
    #pragma unroll
    for (int ks = 0; ks < 8; ++ks) {
        const int k8 = ks * 8;
        qa[ks][0] = fbits(Ps[(m0 + g) * 68 + k8 + e]);
        qa[ks][1] = fbits(Ps[(m0 + g + 8) * 68 + k8 + e]);
        qa[ks][2] = fbits(Ps[(m0 + g) * 68 + k8 + e + 4]);
        qa[ks][3] = fbits(Ps[(m0 + g + 8) * 68 + k8 + e + 4]);
    }

    float o_[8][4] = {};
    float mrow[2] = {-1e30f, -1e30f}, lrow[2] = {0.f, 0.f};

    const int NIT = SEQ / 64;
    CP_WAIT0();
    __syncthreads();

    for (int it = 0; it < NIT; ++it) {
        const int bf = it & 1;
        if (it + 1 < NIT) {
            const int nb = bf ^ 1;
            const int kt = (it + 1) * 64;
            #pragma unroll
            for (int i = 0; i < 4; ++i) {
                const int key = lkey + 16 * i;
                cp16(&Ks[nb * 64 * 68 + key * 68 + lq4],
                     k + base + (size_t)(kt + key) * EMBED + lq4);
                cp16(&Vs[nb * 64 * 72 + key * 72 + lq4],
                     v + base + (size_t)(kt + key) * EMBED + lq4);
            }
            CP_COMMIT();
        }
        const float* Kb = Ks + bf * 64 * 68;
        const float* Vb = Vs + bf * 64 * 72;

        // S = Q * K^T : 16 rows x 64 keys per warp (Q frags from registers)
        float s[8][4] = {};
        #pragma unroll
        for (int ks = 0; ks < 8; ++ks) {
            const int k8 = ks * 8;
            #pragma unroll
            for (int n = 0; n < 8; ++n) {
                uint32_t bb[2];
                bb[0] = fbits(Kb[(n * 8 + g) * 68 + k8 + e]);
                bb[1] = fbits(Kb[(n * 8 + g) * 68 + k8 + e + 4]);
                mma_tf32(s[n], qa[ks], bb);
            }
        }

        // online softmax per row-half
        #pragma unroll
        for (int hh = 0; hh < 2; ++hh) {
            const int ci = hh * 2;
            float mx = -1e30f;
            #pragma unroll
            for (int n = 0; n < 8; ++n)
                mx = fmaxf(mx, fmaxf(s[n][ci], s[n][ci + 1]));
            mx = fmaxf(mx, __shfl_xor_sync(0xffffffffu, mx, 1));
            mx = fmaxf(mx, __shfl_xor_sync(0xffffffffu, mx, 2));
            const float mn = fmaxf(mrow[hh], mx);
            const float al = __expf(mrow[hh] - mn);
            mrow[hh] = mn;
            float sum = 0.f;
            #pragma unroll
            for (int n = 0; n < 8; ++n) {
                const float p0 = __expf(s[n][ci] - mn);
                const float p1 = __expf(s[n][ci + 1] - mn);
                s[n][ci] = p0; s[n][ci + 1] = p1;
                sum += p0 + p1;
            }
            sum += __shfl_xor_sync(0xffffffffu, sum, 1);
            sum += __shfl_xor_sync(0xffffffffu, sum, 2);
            lrow[hh] = lrow[hh] * al + sum;
            const int pr = (m0 + g + 8 * hh) * 68;
            #pragma unroll
            for (int n = 0; n < 8; ++n) {
                o_[n][ci] *= al; o_[n][ci + 1] *= al;
                *(float2*)&Ps[pr + n * 8 + 2 * e] =
                    make_float2(rna(s[n][ci]), rna(s[n][ci + 1]));
            }
        }
        __syncwarp();   // Ps rows are per-warp private

        // O += P * V
        #pragma unroll
        for (int ks = 0; ks < 8; ++ks) {
            const int k8 = ks * 8;
            uint32_t a[4];
            a[0] = fbits(Ps[(m0 + g) * 68 + k8 + e]);
            a[1] = fbits(Ps[(m0 + g + 8) * 68 + k8 + e]);
            a[2] = fbits(Ps[(m0 + g) * 68 + k8 + e + 4]);
            a[3] = fbits(Ps[(m0 + g + 8) * 68 + k8 + e + 4]);
            #pragma unroll
            for (int n = 0; n < 8; ++n) {
                uint32_t bb[2];
                bb[0] = fbits(Vb[(k8 + e) * 72 + n * 8 + g]);
                bb[1] = fbits(Vb[(k8 + e + 4) * 72 + n * 8 + g]);
                mma_tf32(o_[n], a, bb);
            }
        }

        CP_WAIT0();
        __syncthreads();
    }

    // epilogue: O /= l, rna, write to [B*S, EMBED] at head offset
    #pragma unroll
    for (int hh = 0; hh < 2; ++hh) {
        const float inv = 1.0f / lrow[hh];
        const int row = qrow0 + m0 + g + 8 * hh;
        const int ci = hh * 2;
        #pragma unroll
        for (int n = 0; n < 8; ++n) {
            *(float2*)(o + base + (size_t)row * EMBED + n * 8 + 2 * e) =
                make_float2(rna(o_[n][ci] * inv), rna(o_[n][ci + 1] * inv));
        }
    }
}

// ---------------------------------------------------------------------------
extern "C" void kernel_launch(void* const* d_in, const int* in_sizes, int n_in,
                              void* d_out, int out_size)
{
    const float* x  = (const float*)d_in[0];
    const float* Wq = (const float*)d_in[1];
    const float* bq = (const float*)d_in[2];
    const float* Wk = (const float*)d_in[3];
    const float* bk = (const float*)d_in[4];
    const float* Wv = (const float*)d_in[5];
    const float* bv = (const float*)d_in[6];
    const float* Wo = (const float*)d_in[7];
    const float* bo = (const float*)d_in[8];
    float* out = (float*)d_out;

    float *q, *k, *v, *oa, *xr, *wt, *wo, *bc;
    cudaGetSymbolAddress((void**)&q,  g_q);
    cudaGetSymbolAddress((void**)&k,  g_k);
    cudaGetSymbolAddress((void**)&v,  g_v);
    cudaGetSymbolAddress((void**)&oa, g_o);
    cudaGetSymbolAddress((void**)&xr, g_xr);
    cudaGetSymbolAddress((void**)&wt, g_wt);
    cudaGetSymbolAddress((void**)&wo, g_wo);
    cudaGetSymbolAddress((void**)&bc, g_bc);

    const int nx4 = MTOT * EMBED / 4;
    preround<<<(nx4 + 255) / 256, 256>>>(x, xr, 1.0f, nx4);
    transpose_all<<<dim3(EMBED / 32, EMBED / 32, 4), 256>>>(Wq, Wk, Wv, Wo, wt, wo);
    bias_cat<<<(3 * EMBED + 255) / 256, 256>>>(bq, bk, bv, bc);

    cudaFuncSetAttribute(gemm_big, cudaFuncAttributeMaxDynamicSharedMemorySize,
                         GEMM_SMEM);
    cudaFuncSetAttribute(flash_v3, cudaFuncAttributeMaxDynamicSharedMemorySize,
                         FLASH_SMEM);

    // fused QKV: grid (24, 64); Wo: grid (8, 64)
    gemm_big<<<dim3(24, MTOT / 128), 256, GEMM_SMEM>>>(xr, wt, bc, q, k, v, 1);

    flash_v3<<<dim3(BATCH * NHEADS, SEQ / 128), 256, FLASH_SMEM>>>(q, k, v, oa);

    gemm_big<<<dim3(8, MTOT / 128), 256, GEMM_SMEM>>>(oa, wo, bo, out, out, out, 0);
}

// round 8
// speedup vs baseline: 5.6092x; 1.0238x over previous
#include <cuda_runtime.h>
#include <cstdint>

#define EMBED 1024
#define NHEADS 16
#define HDIM 64
#define BATCH 4
#define SEQ 2048
#define MTOT (BATCH * SEQ)   // 8192

// Scratch (static device globals: allowed; no runtime allocation)
__device__ float g_q [(size_t)MTOT * EMBED];
__device__ float g_k [(size_t)MTOT * EMBED];
__device__ float g_v [(size_t)MTOT * EMBED];
__device__ float g_o [(size_t)MTOT * EMBED];
__device__ float g_xr[(size_t)MTOT * EMBED];
__device__ float g_wt[(size_t)3 * EMBED * EMBED];   // [Wq;Wk;Wv] transposed [N][K]
__device__ float g_wo[(size_t)EMBED * EMBED];       // Wo transposed [N][K]
__device__ float g_bc[3 * EMBED];                   // concat bias (q scaled)

__device__ __forceinline__ float rna(float x) {
    float r;
    asm("cvt.rna.tf32.f32 %0, %1;" : "=f"(r) : "f"(x));
    return r;
}
__device__ __forceinline__ uint32_t fbits(float x) { return __float_as_uint(x); }

__device__ __forceinline__ void mma_tf32(float c[4], const uint32_t a[4],
                                         const uint32_t b[2]) {
    asm volatile(
        "mma.sync.aligned.m16n8k8.row.col.f32.tf32.tf32.f32 "
        "{%0,%1,%2,%3}, {%4,%5,%6,%7}, {%8,%9}, {%0,%1,%2,%3};"
        : "+f"(c[0]), "+f"(c[1]), "+f"(c[2]), "+f"(c[3])
        : "r"(a[0]), "r"(a[1]), "r"(a[2]), "r"(a[3]), "r"(b[0]), "r"(b[1]));
}

__device__ __forceinline__ void cp16(void* dst_smem, const void* src) {
    uint32_t d = (uint32_t)__cvta_generic_to_shared(dst_smem);
    asm volatile("cp.async.cg.shared.global [%0], [%1], 16;" :: "r"(d), "l"(src));
}
#define CP_COMMIT() asm volatile("cp.async.commit_group;")
#define CP_WAIT0()  asm volatile("cp.async.wait_group 0;" ::: "memory")

// ---------------------------------------------------------------------------
// elementwise rna (for x)
// ---------------------------------------------------------------------------
__global__ void preround(const float* __restrict__ s, float* __restrict__ d,
                         float sc, int n4)
{
    int i = blockIdx.x * 256 + threadIdx.x;
    if (i < n4) {
        float4 v = ((const float4*)s)[i];
        v.x = rna(v.x * sc); v.y = rna(v.y * sc);
        v.z = rna(v.z * sc); v.w = rna(v.w * sc);
        ((float4*)d)[i] = v;
    }
}

// ---------------------------------------------------------------------------
// all 4 weight transposes in one launch (z picks matrix); Wq folded * 1/8
// ---------------------------------------------------------------------------
__global__ __launch_bounds__(256) void transpose_all(
    const float* __restrict__ Wq, const float* __restrict__ Wk,
    const float* __restrict__ Wv, const float* __restrict__ Wo,
    float* __restrict__ wt, float* __restrict__ wo)
{
    __shared__ float tl[32][33];
    const int z = blockIdx.z;
    const float* src = (z == 0) ? Wq : (z == 1) ? Wk : (z == 2) ? Wv : Wo;
    float* dst = (z == 3) ? wo : wt + (size_t)z * EMBED * EMBED;
    const float sc = (z == 0) ? 0.125f : 1.0f;

    const int tx = threadIdx.x & 31, ty = threadIdx.x >> 5;  // 32 x 8
    const int x0 = blockIdx.x * 32, y0 = blockIdx.y * 32;
    #pragma unroll
    for (int j = 0; j < 32; j += 8)
        tl[ty + j][tx] = rna(src[(size_t)(y0 + ty + j) * EMBED + x0 + tx] * sc);
    __syncthreads();
    #pragma unroll
    for (int j = 0; j < 32; j += 8)
        dst[(size_t)(x0 + ty + j) * EMBED + y0 + tx] = tl[tx][ty + j];
}

// bias concat: bc[0:1024)=bq*0.125, [1024:2048)=bk, [2048:3072)=bv
__global__ void bias_cat(const float* __restrict__ bq, const float* __restrict__ bk,
                         const float* __restrict__ bv, float* __restrict__ bc)
{
    int i = blockIdx.x * 256 + threadIdx.x;
    if (i < EMBED)          bc[i] = bq[i] * 0.125f;
    else if (i < 2 * EMBED) bc[i] = bk[i - EMBED];
    else if (i < 3 * EMBED) bc[i] = bv[i - 2 * EMBED];
}

// ---------------------------------------------------------------------------
// tf32 mma.sync GEMM with k-permuted fragments (all frag loads = LDS.64).
// Block 128x128, 8 warps (4M x 2N), warp tile 32x64, BK=32, 2-stage cp.async,
// 2 CTAs/SM.  Tiles staged [row][k] with pad 40 (stride = 8 mod 32 ->
// conflict-free 64-bit fragment loads per half-warp).
// smem: As[2][128][40] + Bs[2][128][40] = 81920 B
// ---------------------------------------------------------------------------
#define GPAD 40
#define GEMM_SMEM (2 * 2 * 128 * GPAD * 4)

__global__ __launch_bounds__(256, 2) void gemm_big(
    const float* __restrict__ A, const float* __restrict__ BT,
    const float* __restrict__ bias, float* __restrict__ D0,
    float* __restrict__ D1, float* __restrict__ D2, int round_out)
{
    extern __shared__ float sh[];
    float* As = sh;                      // [2][128][40]
    float* Bs = sh + 2 * 128 * GPAD;     // [2][128][40]

    const int t = threadIdx.x;
    const int lane = t & 31, warp = t >> 5;
    const int g = lane >> 2, e = lane & 3;
    const int m0 = (warp & 3) * 32, n0 = (warp >> 2) * 64;

    const int row0 = blockIdx.y * 128;
    const int bx = blockIdx.x;
    const int id = bx >> 3;                       // which output matrix
    const int col0 = (bx & 7) * 128;              // col within matrix
    float* D = (id == 0) ? D0 : (id == 1) ? D1 : D2;

    // loaders: tiles staged [row][k]; thread covers (row = t>>3 (+32p), k=(t&7)*4)
    const int lr = t >> 3, lk = (t & 7) * 4;
    const float* Ab = A  + (size_t)(row0 + lr) * EMBED + lk;
    const float* Bb = BT + (size_t)(bx * 128 + lr) * EMBED + lk;

    #define GREFILL(k0, buf) do {                                              \
        float* sA = As + (buf) * 128 * GPAD;                                   \
        float* sB = Bs + (buf) * 128 * GPAD;                                   \
        _Pragma("unroll")                                                      \
        for (int p = 0; p < 4; ++p) {                                          \
            cp16(&sA[(lr + 32 * p) * GPAD + lk], Ab + (size_t)(32 * p) * EMBED + (k0)); \
            cp16(&sB[(lr + 32 * p) * GPAD + lk], Bb + (size_t)(32 * p) * EMBED + (k0)); \
        }                                                                      \
        CP_COMMIT();                                                           \
    } while (0)

    GREFILL(0, 0);

    float acc[2][8][4] = {};
    const int NIT = EMBED / 32;

    for (int it = 0; it < NIT; ++it) {
        CP_WAIT0();
        __syncthreads();
        if (it + 1 < NIT) GREFILL((it + 1) * 32, (it + 1) & 1);

        const float* Ac = As + (it & 1) * 128 * GPAD;
        const float* Bc = Bs + (it & 1) * 128 * GPAD;

        #pragma unroll
        for (int ks = 0; ks < 4; ++ks) {
            const int kp = ks * 8 + 2 * e;         // permuted: lanes e -> 2e,2e+1
            uint32_t a[2][4];
            #pragma unroll
            for (int mt = 0; mt < 2; ++mt) {
                const int r = m0 + mt * 16 + g;
                float2 p0 = *(const float2*)&Ac[r * GPAD + kp];
                float2 p1 = *(const float2*)&Ac[(r + 8) * GPAD + kp];
                a[mt][0] = fbits(p0.x); a[mt][2] = fbits(p0.y);
                a[mt][1] = fbits(p1.x); a[mt][3] = fbits(p1.y);
            }
            #pragma unroll
            for (int n = 0; n < 8; ++n) {
                const int br = n0 + n * 8 + g;
                float2 q = *(const float2*)&Bc[br * GPAD + kp];
                uint32_t b[2] = {fbits(q.x), fbits(q.y)};
                mma_tf32(acc[0][n], a[0], b);
                mma_tf32(acc[1][n], a[1], b);
            }
        }
        __syncthreads();
    }

    // epilogue
    #pragma unroll
    for (int mt = 0; mt < 2; ++mt) {
        const int r = row0 + m0 + mt * 16 + g;
        #pragma unroll
        for (int n = 0; n < 8; ++n) {
            const int cl = col0 + n0 + n * 8 + 2 * e;         // col in matrix
            const int cb = bx * 128 + n0 + n * 8 + 2 * e;     // col in bias buf
            const float b0 = bias[cb], b1 = bias[cb + 1];
            float v00 = acc[mt][n][0] + b0, v01 = acc[mt][n][1] + b1;
            float v10 = acc[mt][n][2] + b0, v11 = acc[mt][n][3] + b1;
            if (round_out) { v00 = rna(v00); v01 = rna(v01);
                             v10 = rna(v10); v11 = rna(v11); }
            *(float2*)&D[(size_t)r * EMBED + cl]       = make_float2(v00, v01);
            *(float2*)&D[(size_t)(r + 8) * EMBED + cl] = make_float2(v10, v11);
        }
    }
}

// ---------------------------------------------------------------------------
// Flash attention v4: Q-block 128 rows, 8 warps x 16 rows, Bc=64,
// 2-stage cp.async K/V, 2 CTAs/SM.  Q/K use permuted k-lanes so S-mma
// fragment loads are LDS.64 (K pad 72: stride=8 mod 32, conflict-free).
// PV mma stays standard order (Ps pad 68, V pad 72 — conflict-free .32).
// smem: Ks[2][64][72] Vs[2][64][72] Ps[128][68] = 108544 B
// ---------------------------------------------------------------------------
#define KPAD 72
#define VPAD 72
#define PPAD 68
#define FKS_OFF 0
#define FVS_OFF (2 * 64 * KPAD)
#define FPS_OFF (FVS_OFF + 2 * 64 * VPAD)
#define FLASH_SMEM ((FPS_OFF + 128 * PPAD) * 4)

__global__ __launch_bounds__(256, 2) void flash_v4(
    const float* __restrict__ q, const float* __restrict__ k,
    const float* __restrict__ v, float* __restrict__ o)
{
    extern __shared__ float shf[];
    float* Ks = shf + FKS_OFF;
    float* Vs = shf + FVS_OFF;
    float* Ps = shf + FPS_OFF;

    const int t = threadIdx.x;
    const int lane = t & 31, warp = t >> 5;
    const int g = lane >> 2, e = lane & 3;
    const int m0 = warp * 16;

    const int bh = blockIdx.x;
    const int b = bh >> 4, h = bh & 15;
    const int qrow0 = blockIdx.y * 128;
    const size_t base = ((size_t)b * SEQ) * EMBED + (size_t)h * HDIM;

    const int lkey = t >> 4;          // 0..15
    const int lq4  = (t & 15) * 4;    // 0..60

    // prefetch K/V tile 0 into buf 0
    #pragma unroll
    for (int i = 0; i < 4; ++i) {
        const int key = lkey + 16 * i;
        cp16(&Ks[key * KPAD + lq4], k + base + (size_t)key * EMBED + lq4);
        cp16(&Vs[key * VPAD + lq4], v + base + (size_t)key * EMBED + lq4);
    }
    CP_COMMIT();

    // stage Q (128x64) into Ps, then hoist PERMUTED fragments to registers
    #pragma unroll
    for (int i = 0; i < 8; ++i) {
        const int row = lkey + 16 * i;
        *(float4*)&Ps[row * PPAD + lq4] =
            *(const float4*)(q + base + (size_t)(qrow0 + row) * EMBED + lq4);
    }
    __syncthreads();
    uint32_t qa[8][4];
    #pragma unroll
    for (int ks = 0; ks < 8; ++ks) {
        const int kp = ks * 8 + 2 * e;
        float2 p0 = *(const float2*)&Ps[(m0 + g) * PPAD + kp];
        float2 p1 = *(const float2*)&Ps[(m0 + g + 8) * PPAD + kp];
        qa[ks][0] = fbits(p0.x); qa[ks][2] = fbits(p0.y);
        qa[ks][1] = fbits(p1.x); qa[ks][3] = fbits(p1.y);
    }

    float o_[8][4] = {};
    float mrow[2] = {-1e30f, -1e30f}, lrow[2] = {0.f, 0.f};

    const int NIT = SEQ / 64;
    CP_WAIT0();
    __syncthreads();

    for (int it = 0; it < NIT; ++it) {
        const int bf = it & 1;
        if (it + 1 < NIT) {
            const int nb = bf ^ 1;
            const int kt = (it + 1) * 64;
            #pragma unroll
            for (int i = 0; i < 4; ++i) {
                const int key = lkey + 16 * i;
                cp16(&Ks[nb * 64 * KPAD + key * KPAD + lq4],
                     k + base + (size_t)(kt + key) * EMBED + lq4);
                cp16(&Vs[nb * 64 * VPAD + key * VPAD + lq4],
                     v + base + (size_t)(kt + key) * EMBED + lq4);
            }
            CP_COMMIT();
        }
        const float* Kb = Ks + bf * 64 * KPAD;
        const float* Vb = Vs + bf * 64 * VPAD;

        // S = Q * K^T : permuted k-lanes, K frags via LDS.64
        float s[8][4] = {};
        #pragma unroll
        for (int ks = 0; ks < 8; ++ks) {
            const int kp = ks * 8 + 2 * e;
            #pragma unroll
            for (int n = 0; n < 8; ++n) {
                float2 kk = *(const float2*)&Kb[(n * 8 + g) * KPAD + kp];
                uint32_t bb[2] = {fbits(kk.x), fbits(kk.y)};
                mma_tf32(s[n], qa[ks], bb);
            }
        }

        // online softmax per row-half
        #pragma unroll
        for (int hh = 0; hh < 2; ++hh) {
            const int ci = hh * 2;
            float mx = -1e30f;
            #pragma unroll
            for (int n = 0; n < 8; ++n)
                mx = fmaxf(mx, fmaxf(s[n][ci], s[n][ci + 1]));
            mx = fmaxf(mx, __shfl_xor_sync(0xffffffffu, mx, 1));
            mx = fmaxf(mx, __shfl_xor_sync(0xffffffffu, mx, 2));
            const float mn = fmaxf(mrow[hh], mx);
            const float al = __expf(mrow[hh] - mn);
            mrow[hh] = mn;
            float sum = 0.f;
            #pragma unroll
            for (int n = 0; n < 8; ++n) {
                const float p0 = __expf(s[n][ci] - mn);
                const float p1 = __expf(s[n][ci + 1] - mn);
                s[n][ci] = p0; s[n][ci + 1] = p1;
                sum += p0 + p1;
            }
            sum += __shfl_xor_sync(0xffffffffu, sum, 1);
            sum += __shfl_xor_sync(0xffffffffu, sum, 2);
            lrow[hh] = lrow[hh] * al + sum;
            const int pr = (m0 + g + 8 * hh) * PPAD;
            #pragma unroll
            for (int n = 0; n < 8; ++n) {
                o_[n][ci] *= al; o_[n][ci + 1] *= al;
                *(float2*)&Ps[pr + n * 8 + 2 * e] =
                    make_float2(rna(s[n][ci]), rna(s[n][ci + 1]));
            }
        }
        __syncwarp();   // Ps rows are per-warp private

        // O += P * V  (standard k-order)
        #pragma unroll
        for (int ks = 0; ks < 8; ++ks) {
            const int k8 = ks * 8;
            uint32_t a[4];
            a[0] = fbits(Ps[(m0 + g) * PPAD + k8 + e]);
            a[1] = fbits(Ps[(m0 + g + 8) * PPAD + k8 + e]);
            a[2] = fbits(Ps[(m0 + g) * PPAD + k8 + e + 4]);
            a[3] = fbits(Ps[(m0 + g + 8) * PPAD + k8 + e + 4]);
            #pragma unroll
            for (int n = 0; n < 8; ++n) {
                uint32_t bb[2];
                bb[0] = fbits(Vb[(k8 + e) * VPAD + n * 8 + g]);
                bb[1] = fbits(Vb[(k8 + e + 4) * VPAD + n * 8 + g]);
                mma_tf32(o_[n], a, bb);
            }
        }

        CP_WAIT0();
        __syncthreads();
    }

    // epilogue: O /= l, rna, write to [B*S, EMBED] at head offset
    #pragma unroll
    for (int hh = 0; hh < 2; ++hh) {
        const float inv = 1.0f / lrow[hh];
        const int row = qrow0 + m0 + g + 8 * hh;
        const int ci = hh * 2;
        #pragma unroll
        for (int n = 0; n < 8; ++n) {
            *(float2*)(o + base + (size_t)row * EMBED + n * 8 + 2 * e) =
                make_float2(rna(o_[n][ci] * inv), rna(o_[n][ci + 1] * inv));
        }
    }
}

// ---------------------------------------------------------------------------
extern "C" void kernel_launch(void* const* d_in, const int* in_sizes, int n_in,
                              void* d_out, int out_size)
{
    const float* x  = (const float*)d_in[0];
    const float* Wq = (const float*)d_in[1];
    const float* bq = (const float*)d_in[2];
    const float* Wk = (const float*)d_in[3];
    const float* bk = (const float*)d_in[4];
    const float* Wv = (const float*)d_in[5];
    const float* bv = (const float*)d_in[6];
    const float* Wo = (const float*)d_in[7];
    const float* bo = (const float*)d_in[8];
    float* out = (float*)d_out;

    float *q, *k, *v, *oa, *xr, *wt, *wo, *bc;
    cudaGetSymbolAddress((void**)&q,  g_q);
    cudaGetSymbolAddress((void**)&k,  g_k);
    cudaGetSymbolAddress((void**)&v,  g_v);
    cudaGetSymbolAddress((void**)&oa, g_o);
    cudaGetSymbolAddress((void**)&xr, g_xr);
    cudaGetSymbolAddress((void**)&wt, g_wt);
    cudaGetSymbolAddress((void**)&wo, g_wo);
    cudaGetSymbolAddress((void**)&bc, g_bc);

    const int nx4 = MTOT * EMBED / 4;
    preround<<<(nx4 + 255) / 256, 256>>>(x, xr, 1.0f, nx4);
    transpose_all<<<dim3(EMBED / 32, EMBED / 32, 4), 256>>>(Wq, Wk, Wv, Wo, wt, wo);
    bias_cat<<<(3 * EMBED + 255) / 256, 256>>>(bq, bk, bv, bc);

    cudaFuncSetAttribute(gemm_big, cudaFuncAttributeMaxDynamicSharedMemorySize,
                         GEMM_SMEM);
    cudaFuncSetAttribute(flash_v4, cudaFuncAttributeMaxDynamicSharedMemorySize,
                         FLASH_SMEM);

    // fused QKV: grid (24, 64); Wo: grid (8, 64)
    gemm_big<<<dim3(24, MTOT / 128), 256, GEMM_SMEM>>>(xr, wt, bc, q, k, v, 1);

    flash_v4<<<dim3(BATCH * NHEADS, SEQ / 128), 256, FLASH_SMEM>>>(q, k, v, oa);

    gemm_big<<<dim3(8, MTOT / 128), 256, GEMM_SMEM>>>(oa, wo, bo, out, out, out, 0);
}